// round 6
// baseline (speedup 1.0000x reference)
#include <cuda_runtime.h>
#include <cuda_fp16.h>
#include <cstdint>
#include <math.h>

#define BB 4
#define TT 2048
#define CC 1024
#define HH 16
#define DD 64
#define FF 4096
#define MROWS (BB*TT)   // 8192

// ---------------- scratch (static device globals; no allocation) -------------
__device__ float g_xn[MROWS*CC];
__device__ float g_q[MROWS*CC];
__device__ float g_k[MROWS*CC];
__device__ float g_v[MROWS*CC];
__device__ float g_gate[MROWS*CC];
__device__ float g_o[MROWS*CC];
__device__ float g_x1[MROWS*CC];
__device__ float g_beta[MROWS*HH];
__device__ float g_gg[MROWS*FF];
__device__ float g_uu[MROWS*FF];
// fp16 buffers
__device__ __align__(16) __half g_a_hi[MROWS*FF];
__device__ __align__(16) __half g_a_lo[MROWS*FF];
__device__ __align__(16) __half g_w_hi[FF*CC];

// ================= PTX helpers (sm_80-era, plain-target safe) ================
__device__ __forceinline__ uint32_t smem_u32(const void* p) {
    return (uint32_t)__cvta_generic_to_shared(p);
}
__device__ __forceinline__ void cp16(uint32_t dst, const void* src) {
    asm volatile("cp.async.cg.shared.global [%0], [%1], 16;\n" :: "r"(dst), "l"(src));
}
__device__ __forceinline__ void cp_commit() {
    asm volatile("cp.async.commit_group;\n" ::: "memory");
}
__device__ __forceinline__ void ldsm4(uint32_t* d, uint32_t addr) {
    asm volatile("ldmatrix.sync.aligned.m8n8.x4.shared.b16 {%0,%1,%2,%3}, [%4];"
                 : "=r"(d[0]), "=r"(d[1]), "=r"(d[2]), "=r"(d[3]) : "r"(addr));
}
__device__ __forceinline__ void mma_fp16(float* c, const uint32_t* a,
                                         uint32_t b0, uint32_t b1) {
    asm volatile(
        "mma.sync.aligned.m16n8k16.row.col.f32.f16.f16.f32 "
        "{%0,%1,%2,%3}, {%4,%5,%6,%7}, {%8,%9}, {%0,%1,%2,%3};"
        : "+f"(c[0]), "+f"(c[1]), "+f"(c[2]), "+f"(c[3])
        : "r"(a[0]), "r"(a[1]), "r"(a[2]), "r"(a[3]), "r"(b0), "r"(b1));
}

// ================= split-fp16 GEMM via mma.sync ==============================
// C[M,N] = (Ah+Al)[M,K] * Bh[N,K]^T (+ optional residual R), fp32 out.
// 2 passes: Ah*Bh + Al*Bh. CTA 128x128, KT=64, 2 stages (96KB), 2 CTAs/SM.
#define TILE_MN 128
#define KT 64
#define SUB_BYTES (128*128)          // 16KB per tile
#define OFF_A_HI 0
#define OFF_A_LO (SUB_BYTES)
#define OFF_B    (2*SUB_BYTES)
#define STAGE_BYTES (3*SUB_BYTES)    // 48KB
#define GSMEM_TOTAL (2*STAGE_BYTES)  // 96KB

__device__ __forceinline__ void load_tile(const __half* __restrict__ g, int ldk,
                                          int row0, int k0, uint32_t dstbase, int tid) {
#pragma unroll
    for (int i = tid; i < 128 * 8; i += 256) {
        int r = i >> 3;
        int c16 = i & 7;
        const __half* src = g + (size_t)(row0 + r) * ldk + k0 + c16 * 8;
        uint32_t dst = dstbase + r * 128 + (((uint32_t)(c16 ^ (r & 7))) << 4);
        cp16(dst, src);
    }
}

__global__ __launch_bounds__(256, 2)
void gemm_mma(float* __restrict__ C, const float* __restrict__ R,
              const __half* __restrict__ Ah, const __half* __restrict__ Al,
              const __half* __restrict__ Bh, int M, int N, int K) {
    extern __shared__ __align__(1024) char smem[];
    const uint32_t sbase = smem_u32(smem);
    const int tid = threadIdx.x;
    const int wid = tid >> 5;
    const int lane = tid & 31;
    const int wm = wid & 3;
    const int wn = wid >> 2;
    const int bm = blockIdx.y * TILE_MN;
    const int bn = blockIdx.x * TILE_MN;

    const int mi = lane >> 3;
    const int lr = lane & 7;
    const uint32_t a_off = (uint32_t)(wm * 32 + ((mi & 1) << 3) + lr) * 128;
    const uint32_t a_cb = (uint32_t)(mi >> 1);
    const uint32_t b_off = (uint32_t)(wn * 64 + ((mi >> 1) << 3) + lr) * 128;
    const uint32_t b_cb = (uint32_t)(mi & 1);

    float acc[2][8][4];
#pragma unroll
    for (int a = 0; a < 2; a++)
#pragma unroll
        for (int b = 0; b < 8; b++)
#pragma unroll
            for (int c = 0; c < 4; c++) acc[a][b][c] = 0.f;

    const int NC = K / KT;

    load_tile(Ah, K, bm, 0, sbase + OFF_A_HI, tid);
    load_tile(Al, K, bm, 0, sbase + OFF_A_LO, tid);
    load_tile(Bh, K, bn, 0, sbase + OFF_B, tid);
    cp_commit();
    load_tile(Ah, K, bm, KT, sbase + STAGE_BYTES + OFF_A_HI, tid);
    load_tile(Al, K, bm, KT, sbase + STAGE_BYTES + OFF_A_LO, tid);
    load_tile(Bh, K, bn, KT, sbase + STAGE_BYTES + OFF_B, tid);
    cp_commit();

    for (int kc = 0; kc < NC; kc++) {
        const uint32_t sb = sbase + (uint32_t)(kc & 1) * STAGE_BYTES;
        if (kc + 2 < NC) {
            asm volatile("cp.async.wait_group 1;\n" ::: "memory");
        } else {
            asm volatile("cp.async.wait_group 0;\n" ::: "memory");
        }
        __syncthreads();

#pragma unroll
        for (int ki = 0; ki < 4; ki++) {
            uint32_t ah[2][4], al2[2][4], bh[4][4];
            const uint32_t ax = ((uint32_t)(ki * 2) + a_cb) ^ (uint32_t)lr;
            const uint32_t bx = ((uint32_t)(ki * 2) + b_cb) ^ (uint32_t)lr;
#pragma unroll
            for (int mt = 0; mt < 2; mt++) {
                uint32_t aaddr = sb + a_off + (uint32_t)(mt * 2048) + (ax << 4);
                ldsm4(ah[mt], aaddr + OFF_A_HI);
                ldsm4(al2[mt], aaddr + OFF_A_LO);
            }
#pragma unroll
            for (int nt = 0; nt < 4; nt++) {
                uint32_t baddr = sb + b_off + (uint32_t)(nt * 2048) + (bx << 4);
                ldsm4(bh[nt], baddr + OFF_B);
            }
            // 2 separated passes; 16 independent accumulators per pass
#pragma unroll
            for (int sp = 0; sp < 2; sp++) {
#pragma unroll
                for (int mt = 0; mt < 2; mt++)
#pragma unroll
                    for (int nt = 0; nt < 4; nt++)
#pragma unroll
                        for (int h = 0; h < 2; h++) {
                            const uint32_t* a = (sp == 1) ? al2[mt] : ah[mt];
                            mma_fp16(acc[mt][nt * 2 + h], a,
                                     bh[nt][2 * h], bh[nt][2 * h + 1]);
                        }
            }
        }
        __syncthreads();
        if (kc + 2 < NC) {
            const uint32_t pb = sbase + (uint32_t)(kc & 1) * STAGE_BYTES;
            const int k0 = (kc + 2) * KT;
            load_tile(Ah, K, bm, k0, pb + OFF_A_HI, tid);
            load_tile(Al, K, bm, k0, pb + OFF_A_LO, tid);
            load_tile(Bh, K, bn, k0, pb + OFF_B, tid);
            cp_commit();
        }
    }

    const int g = lane >> 2;
    const int t = lane & 3;
#pragma unroll
    for (int mt = 0; mt < 2; mt++) {
        const int row0 = bm + wm * 32 + mt * 16 + g;
#pragma unroll
        for (int n8 = 0; n8 < 8; n8++) {
            const int col = bn + wn * 64 + n8 * 8 + t * 2;
            float* c = acc[mt][n8];
            if (R) {
                const float* r0 = R + (size_t)row0 * N + col;
                const float* r1 = R + (size_t)(row0 + 8) * N + col;
                *(float2*)(C + (size_t)row0 * N + col) =
                    make_float2(c[0] + r0[0], c[1] + r0[1]);
                *(float2*)(C + (size_t)(row0 + 8) * N + col) =
                    make_float2(c[2] + r1[0], c[3] + r1[1]);
            } else {
                *(float2*)(C + (size_t)row0 * N + col)       = make_float2(c[0], c[1]);
                *(float2*)(C + (size_t)(row0 + 8) * N + col) = make_float2(c[2], c[3]);
            }
        }
    }
}

// ---------------- split helpers ----------------------------------------------
__device__ __forceinline__ void split_store_h(__half* hi, __half* lo, int i4, float4 v) {
    __half h0 = __float2half_rn(v.x);
    __half h1 = __float2half_rn(v.y);
    __half h2 = __float2half_rn(v.z);
    __half h3 = __float2half_rn(v.w);
    __half l0 = __float2half_rn(v.x - __half2float(h0));
    __half l1 = __float2half_rn(v.y - __half2float(h1));
    __half l2 = __float2half_rn(v.z - __half2float(h2));
    __half l3 = __float2half_rn(v.w - __half2float(h3));
    ((__half2*)hi)[2 * i4]     = __halves2half2(h0, h1);
    ((__half2*)hi)[2 * i4 + 1] = __halves2half2(h2, h3);
    ((__half2*)lo)[2 * i4]     = __halves2half2(l0, l1);
    ((__half2*)lo)[2 * i4 + 1] = __halves2half2(l2, l3);
}

// weights: fp32 -> fp16 (hi only)
__global__ void cvt_w_k(const float* __restrict__ x, __half* __restrict__ hi, int n4) {
    int i = blockIdx.x * 256 + threadIdx.x;
    if (i >= n4) return;
    float4 v = ((const float4*)x)[i];
    ((__half2*)hi)[2 * i]     = __halves2half2(__float2half_rn(v.x), __float2half_rn(v.y));
    ((__half2*)hi)[2 * i + 1] = __halves2half2(__float2half_rn(v.z), __float2half_rn(v.w));
}

// ---------------- rmsnorm (fused split output) --------------------------------
__global__ void rmsnorm_split_k(const float* __restrict__ x, const float* __restrict__ w,
                                float* __restrict__ y, __half* __restrict__ hi,
                                __half* __restrict__ lo) {
    int row = blockIdx.x;
    const float* xr = x + (size_t)row * CC;
    float* yr = y + (size_t)row * CC;
    float v[4];
    float ss = 0.f;
#pragma unroll
    for (int i = 0; i < 4; i++) {
        v[i] = xr[threadIdx.x + i * 256];
        ss += v[i] * v[i];
    }
#pragma unroll
    for (int off = 16; off; off >>= 1) ss += __shfl_xor_sync(0xffffffffu, ss, off);
    __shared__ float sred[8];
    __shared__ float stot;
    if ((threadIdx.x & 31) == 0) sred[threadIdx.x >> 5] = ss;
    __syncthreads();
    if (threadIdx.x < 8) {
        float t = sred[threadIdx.x];
#pragma unroll
        for (int off = 4; off; off >>= 1) t += __shfl_xor_sync(0xffu, t, off);
        if (threadIdx.x == 0) stot = t;
    }
    __syncthreads();
    float r = rsqrtf(stot / (float)CC + 1e-6f);
#pragma unroll
    for (int i = 0; i < 4; i++)
        yr[threadIdx.x + i * 256] = v[i] * r * w[threadIdx.x + i * 256];
    __syncthreads();
    float4 vv = ((const float4*)yr)[threadIdx.x];
    split_store_h(hi + (size_t)row * CC, lo + (size_t)row * CC, threadIdx.x, vv);
}

// ---------------- beta: fused dot + bias + sigmoid ---------------------------
__global__ __launch_bounds__(512)
void beta_k(const float* __restrict__ xn, const float* __restrict__ bw,
            const float* __restrict__ bias, float* __restrict__ beta) {
    __shared__ float xs[CC];
    const int row = blockIdx.x;
    for (int i = threadIdx.x; i < CC; i += 512) xs[i] = xn[(size_t)row * CC + i];
    __syncthreads();
    const int h = threadIdx.x >> 5;
    const int lane = threadIdx.x & 31;
    const float* w = bw + (size_t)h * CC;
    float acc = 0.f;
#pragma unroll 8
    for (int j = lane; j < CC; j += 32) acc += xs[j] * w[j];
#pragma unroll
    for (int off = 16; off; off >>= 1) acc += __shfl_xor_sync(0xffffffffu, acc, off);
    if (lane == 0) {
        float t = acc + bias[h];
        beta[(size_t)row * HH + h] = 1.f / (1.f + __expf(-t));
    }
}

// ---------------- elementwise helpers ----------------------------------------
__global__ void l2norm_k(float* __restrict__ x) {
    int vec = blockIdx.x * 8 + (threadIdx.x >> 5);
    int lane = threadIdx.x & 31;
    float* p = x + (size_t)vec * 64;
    float a = p[lane], b = p[lane + 32];
    float ss = a * a + b * b;
#pragma unroll
    for (int off = 16; off; off >>= 1) ss += __shfl_xor_sync(0xffffffffu, ss, off);
    float inv = 1.f / fmaxf(sqrtf(ss), 1e-12f);
    p[lane] = a * inv;
    p[lane + 32] = b * inv;
}

__global__ void gate_mul_split_k(const float* __restrict__ gate, const float* __restrict__ o,
                                 __half* __restrict__ hi, __half* __restrict__ lo) {
    int i = blockIdx.x * 256 + threadIdx.x;
    float4 gv = ((const float4*)gate)[i];
    float4 ov = ((const float4*)o)[i];
    float4 r;
    r.x = ov.x / (1.f + __expf(-gv.x));
    r.y = ov.y / (1.f + __expf(-gv.y));
    r.z = ov.z / (1.f + __expf(-gv.z));
    r.w = ov.w / (1.f + __expf(-gv.w));
    split_store_h(hi, lo, i, r);
}

__global__ void silu_mul_split_k(const float* __restrict__ g, const float* __restrict__ u,
                                 __half* __restrict__ hi, __half* __restrict__ lo) {
    int i = blockIdx.x * 256 + threadIdx.x;
    float4 gv = ((const float4*)g)[i];
    float4 uv = ((const float4*)u)[i];
    float4 r;
    r.x = (gv.x / (1.f + __expf(-gv.x))) * uv.x;
    r.y = (gv.y / (1.f + __expf(-gv.y))) * uv.y;
    r.z = (gv.z / (1.f + __expf(-gv.z))) * uv.z;
    r.w = (gv.w / (1.f + __expf(-gv.w))) * uv.w;
    split_store_h(hi, lo, i, r);
}

// ---------------- delta-rule scan --------------------------------------------
__global__ __launch_bounds__(128)
void delta_scan_k(const float* __restrict__ q, const float* __restrict__ k,
                  const float* __restrict__ v, const float* __restrict__ beta,
                  float* __restrict__ o) {
    const int b = blockIdx.x / HH;
    const int h = blockIdx.x % HH;
    const int tid = threadIdx.x;
    const int d = tid >> 1;
    const int s = tid & 1;
    const int cbase = s * 32;

    __shared__ float qs[2][64];
    __shared__ float ks[2][64];

    float Mrow[32];
#pragma unroll
    for (int j = 0; j < 32; j++) Mrow[j] = 0.f;

    const float* qb = q + (size_t)b * TT * CC + h * DD;
    const float* kb = k + (size_t)b * TT * CC + h * DD;
    const float* vb = v + (size_t)b * TT * CC + h * DD;
    const float* bb = beta + (size_t)b * TT * HH + h;
    float* ob = o + (size_t)b * TT * CC + h * DD;

    float rqk = (tid < 64) ? qb[tid] : kb[tid - 64];
    float rv = vb[d];
    float rb = bb[0];

    int buf = 0;
    for (int t = 0; t < TT; t++) {
        if (tid < 64) qs[buf][tid] = rqk; else ks[buf][tid - 64] = rqk;
        __syncthreads();
        float cv = rv, cb = rb;
        if (t + 1 < TT) {
            const int off = (t + 1) * CC;
            rqk = (tid < 64) ? qb[off + tid] : kb[off + tid - 64];
            rv = vb[off + d];
            rb = bb[(t + 1) * HH];
        }
        float po0 = 0.f, po1 = 0.f, pm0 = 0.f, pm1 = 0.f;
#pragma unroll
        for (int j = 0; j < 32; j += 2) {
            float q0 = qs[buf][cbase + j], q1 = qs[buf][cbase + j + 1];
            float k0 = ks[buf][cbase + j], k1 = ks[buf][cbase + j + 1];
            po0 += Mrow[j] * q0;
            po1 += Mrow[j + 1] * q1;
            pm0 += Mrow[j] * k0;
            pm1 += Mrow[j + 1] * k1;
        }
        float po = po0 + po1, pm = pm0 + pm1;
        po += __shfl_xor_sync(0xffffffffu, po, 1);
        pm += __shfl_xor_sync(0xffffffffu, pm, 1);
        float dvb = cb * (cv - pm);
#pragma unroll
        for (int j = 0; j < 32; j++) Mrow[j] += dvb * ks[buf][cbase + j];
        if (s == 0) ob[(size_t)t * CC + d] = po;
        buf ^= 1;
    }
}

// ---------------- launch ------------------------------------------------------
extern "C" void kernel_launch(void* const* d_in, const int* in_sizes, int n_in,
                              void* d_out, int out_size) {
    const float* x       = (const float*)d_in[0];
    const float* norm1_w = (const float*)d_in[3];
    const float* norm2_w = (const float*)d_in[4];
    const float* q_w     = (const float*)d_in[5];
    const float* k_w     = (const float*)d_in[6];
    const float* v_w     = (const float*)d_in[7];
    const float* beta_w  = (const float*)d_in[8];
    const float* beta_b  = (const float*)d_in[9];
    const float* gate_w  = (const float*)d_in[10];
    const float* o_w     = (const float*)d_in[11];
    const float* fg_w    = (const float*)d_in[12];
    const float* fu_w    = (const float*)d_in[13];
    const float* fd_w    = (const float*)d_in[14];
    float* out = (float*)d_out;

    float *xn, *q, *k, *v, *gate, *o, *x1, *beta, *gg, *uu;
    __half *ah, *al, *wh;
    cudaGetSymbolAddress((void**)&xn,   g_xn);
    cudaGetSymbolAddress((void**)&q,    g_q);
    cudaGetSymbolAddress((void**)&k,    g_k);
    cudaGetSymbolAddress((void**)&v,    g_v);
    cudaGetSymbolAddress((void**)&gate, g_gate);
    cudaGetSymbolAddress((void**)&o,    g_o);
    cudaGetSymbolAddress((void**)&x1,   g_x1);
    cudaGetSymbolAddress((void**)&beta, g_beta);
    cudaGetSymbolAddress((void**)&gg,   g_gg);
    cudaGetSymbolAddress((void**)&uu,   g_uu);
    cudaGetSymbolAddress((void**)&ah,   g_a_hi);
    cudaGetSymbolAddress((void**)&al,   g_a_lo);
    cudaGetSymbolAddress((void**)&wh,   g_w_hi);

    cudaFuncSetAttribute(gemm_mma, cudaFuncAttributeMaxDynamicSharedMemorySize,
                         GSMEM_TOTAL);

    auto cvtw = [&](const float* src, int n) {
        cvt_w_k<<<(n / 4 + 255) / 256, 256>>>(src, wh, n / 4);
    };
    auto gemm = [&](float* Cm, const float* R, int N, int K) {
        gemm_mma<<<dim3(N / TILE_MN, MROWS / TILE_MN), 256, GSMEM_TOTAL>>>(
            Cm, R, ah, al, wh, MROWS, N, K);
    };

    // ---- attention branch ----
    rmsnorm_split_k<<<MROWS, 256>>>(x, norm1_w, xn, ah, al);
    cvtw(q_w, CC * CC);    gemm(q,    nullptr, CC, CC);
    cvtw(k_w, CC * CC);    gemm(k,    nullptr, CC, CC);
    cvtw(v_w, CC * CC);    gemm(v,    nullptr, CC, CC);
    cvtw(gate_w, CC * CC); gemm(gate, nullptr, CC, CC);
    beta_k<<<MROWS, 512>>>(xn, beta_w, beta_b, beta);
    l2norm_k<<<(MROWS * HH) / 8, 256>>>(q);
    l2norm_k<<<(MROWS * HH) / 8, 256>>>(k);
    delta_scan_k<<<BB * HH, 128>>>(q, k, v, beta, o);
    gate_mul_split_k<<<MROWS * CC / 4 / 256, 256>>>(gate, o, ah, al);
    cvtw(o_w, CC * CC);    gemm(x1, x, CC, CC);        // x1 = x + attn_out
    // ---- FFN branch ----
    rmsnorm_split_k<<<MROWS, 256>>>(x1, norm2_w, xn, ah, al);
    cvtw(fg_w, FF * CC);   gemm(gg, nullptr, FF, CC);
    cvtw(fu_w, FF * CC);   gemm(uu, nullptr, FF, CC);
    silu_mul_split_k<<<MROWS * FF / 4 / 256, 256>>>(gg, uu, ah, al);
    cvtw(fd_w, CC * FF);   gemm(out, x1, CC, FF);      // out = x1 + ffn_out
}

// round 8
// speedup vs baseline: 1.2735x; 1.2735x over previous
#include <cuda_runtime.h>
#include <cuda_fp16.h>
#include <cstdint>
#include <math.h>

#define BB 4
#define TT 2048
#define CC 1024
#define HH 16
#define DD 64
#define FF 4096
#define MROWS (BB*TT)   // 8192

// ---------------- scratch (static device globals; no allocation) -------------
__device__ float g_xn[MROWS*CC];
__device__ float g_q[MROWS*CC];
__device__ float g_k[MROWS*CC];
__device__ float g_v[MROWS*CC];
__device__ float g_gate[MROWS*CC];
__device__ float g_o[MROWS*CC];
__device__ float g_x1[MROWS*CC];
__device__ float g_beta[MROWS*HH];
__device__ float g_gg[MROWS*FF];
__device__ float g_uu[MROWS*FF];
// fp16 buffers
__device__ __align__(16) __half g_a_hi[MROWS*FF];
__device__ __align__(16) __half g_a_lo[MROWS*FF];
__device__ __align__(16) __half g_w_hi[FF*CC];

// ================= PTX helpers (sm_80-era, plain-target safe) ================
__device__ __forceinline__ uint32_t smem_u32(const void* p) {
    return (uint32_t)__cvta_generic_to_shared(p);
}
__device__ __forceinline__ void cp16(uint32_t dst, const void* src) {
    asm volatile("cp.async.cg.shared.global [%0], [%1], 16;\n" :: "r"(dst), "l"(src));
}
__device__ __forceinline__ void cp_commit() {
    asm volatile("cp.async.commit_group;\n" ::: "memory");
}
__device__ __forceinline__ void ldsm4(uint32_t* d, uint32_t addr) {
    asm volatile("ldmatrix.sync.aligned.m8n8.x4.shared.b16 {%0,%1,%2,%3}, [%4];"
                 : "=r"(d[0]), "=r"(d[1]), "=r"(d[2]), "=r"(d[3]) : "r"(addr));
}
__device__ __forceinline__ void mma_fp16(float* c, const uint32_t* a,
                                         uint32_t b0, uint32_t b1) {
    asm volatile(
        "mma.sync.aligned.m16n8k16.row.col.f32.f16.f16.f32 "
        "{%0,%1,%2,%3}, {%4,%5,%6,%7}, {%8,%9}, {%0,%1,%2,%3};"
        : "+f"(c[0]), "+f"(c[1]), "+f"(c[2]), "+f"(c[3])
        : "r"(a[0]), "r"(a[1]), "r"(a[2]), "r"(a[3]), "r"(b0), "r"(b1));
}

// ================= split-fp16 GEMM via mma.sync ==============================
// C[M,N] = (Ah+Al)[M,K] * Bh[N,K]^T (+ optional residual R), fp32 out.
// 2 passes: Ah*Bh + Al*Bh. CTA 128x128, KT=64, 2 stages (96KB), 1 CTA/SM
// (accumulators must stay in registers; 2 CTAs/SM forced spills in R6).
#define TILE_MN 128
#define KT 64
#define SUB_BYTES (128*128)          // 16KB per tile
#define OFF_A_HI 0
#define OFF_A_LO (SUB_BYTES)
#define OFF_B    (2*SUB_BYTES)
#define STAGE_BYTES (3*SUB_BYTES)    // 48KB
#define GSMEM_TOTAL (2*STAGE_BYTES)  // 96KB

__device__ __forceinline__ void load_tile(const __half* __restrict__ g, int ldk,
                                          int row0, int k0, uint32_t dstbase, int tid) {
#pragma unroll
    for (int i = tid; i < 128 * 8; i += 256) {
        int r = i >> 3;
        int c16 = i & 7;
        const __half* src = g + (size_t)(row0 + r) * ldk + k0 + c16 * 8;
        uint32_t dst = dstbase + r * 128 + (((uint32_t)(c16 ^ (r & 7))) << 4);
        cp16(dst, src);
    }
}

__global__ __launch_bounds__(256, 1)
void gemm_mma(float* __restrict__ C, const float* __restrict__ R,
              const __half* __restrict__ Ah, const __half* __restrict__ Al,
              const __half* __restrict__ Bh, int M, int N, int K) {
    extern __shared__ __align__(1024) char smem[];
    const uint32_t sbase = smem_u32(smem);
    const int tid = threadIdx.x;
    const int wid = tid >> 5;
    const int lane = tid & 31;
    const int wm = wid & 3;
    const int wn = wid >> 2;
    const int bm = blockIdx.y * TILE_MN;
    const int bn = blockIdx.x * TILE_MN;

    const int mi = lane >> 3;
    const int lr = lane & 7;
    const uint32_t a_off = (uint32_t)(wm * 32 + ((mi & 1) << 3) + lr) * 128;
    const uint32_t a_cb = (uint32_t)(mi >> 1);
    const uint32_t b_off = (uint32_t)(wn * 64 + ((mi >> 1) << 3) + lr) * 128;
    const uint32_t b_cb = (uint32_t)(mi & 1);

    float acc[2][8][4];
#pragma unroll
    for (int a = 0; a < 2; a++)
#pragma unroll
        for (int b = 0; b < 8; b++)
#pragma unroll
            for (int c = 0; c < 4; c++) acc[a][b][c] = 0.f;

    const int NC = K / KT;

    load_tile(Ah, K, bm, 0, sbase + OFF_A_HI, tid);
    load_tile(Al, K, bm, 0, sbase + OFF_A_LO, tid);
    load_tile(Bh, K, bn, 0, sbase + OFF_B, tid);
    cp_commit();
    load_tile(Ah, K, bm, KT, sbase + STAGE_BYTES + OFF_A_HI, tid);
    load_tile(Al, K, bm, KT, sbase + STAGE_BYTES + OFF_A_LO, tid);
    load_tile(Bh, K, bn, KT, sbase + STAGE_BYTES + OFF_B, tid);
    cp_commit();

    for (int kc = 0; kc < NC; kc++) {
        const uint32_t sb = sbase + (uint32_t)(kc & 1) * STAGE_BYTES;
        if (kc + 2 < NC) {
            asm volatile("cp.async.wait_group 1;\n" ::: "memory");
        } else {
            asm volatile("cp.async.wait_group 0;\n" ::: "memory");
        }
        __syncthreads();

#pragma unroll
        for (int ki = 0; ki < 4; ki++) {
            uint32_t ah[2][4], al2[2][4], bh[4][4];
            const uint32_t ax = ((uint32_t)(ki * 2) + a_cb) ^ (uint32_t)lr;
            const uint32_t bx = ((uint32_t)(ki * 2) + b_cb) ^ (uint32_t)lr;
#pragma unroll
            for (int mt = 0; mt < 2; mt++) {
                uint32_t aaddr = sb + a_off + (uint32_t)(mt * 2048) + (ax << 4);
                ldsm4(ah[mt], aaddr + OFF_A_HI);
                ldsm4(al2[mt], aaddr + OFF_A_LO);
            }
#pragma unroll
            for (int nt = 0; nt < 4; nt++) {
                uint32_t baddr = sb + b_off + (uint32_t)(nt * 2048) + (bx << 4);
                ldsm4(bh[nt], baddr + OFF_B);
            }
            // 2 separated passes; 16 independent accumulators per pass
#pragma unroll
            for (int sp = 0; sp < 2; sp++) {
#pragma unroll
                for (int mt = 0; mt < 2; mt++)
#pragma unroll
                    for (int nt = 0; nt < 4; nt++)
#pragma unroll
                        for (int h = 0; h < 2; h++) {
                            const uint32_t* a = (sp == 1) ? al2[mt] : ah[mt];
                            mma_fp16(acc[mt][nt * 2 + h], a,
                                     bh[nt][2 * h], bh[nt][2 * h + 1]);
                        }
            }
        }
        __syncthreads();
        if (kc + 2 < NC) {
            const uint32_t pb = sbase + (uint32_t)(kc & 1) * STAGE_BYTES;
            const int k0 = (kc + 2) * KT;
            load_tile(Ah, K, bm, k0, pb + OFF_A_HI, tid);
            load_tile(Al, K, bm, k0, pb + OFF_A_LO, tid);
            load_tile(Bh, K, bn, k0, pb + OFF_B, tid);
            cp_commit();
        }
    }

    const int g = lane >> 2;
    const int t = lane & 3;
#pragma unroll
    for (int mt = 0; mt < 2; mt++) {
        const int row0 = bm + wm * 32 + mt * 16 + g;
#pragma unroll
        for (int n8 = 0; n8 < 8; n8++) {
            const int col = bn + wn * 64 + n8 * 8 + t * 2;
            float* c = acc[mt][n8];
            if (R) {
                const float* r0 = R + (size_t)row0 * N + col;
                const float* r1 = R + (size_t)(row0 + 8) * N + col;
                *(float2*)(C + (size_t)row0 * N + col) =
                    make_float2(c[0] + r0[0], c[1] + r0[1]);
                *(float2*)(C + (size_t)(row0 + 8) * N + col) =
                    make_float2(c[2] + r1[0], c[3] + r1[1]);
            } else {
                *(float2*)(C + (size_t)row0 * N + col)       = make_float2(c[0], c[1]);
                *(float2*)(C + (size_t)(row0 + 8) * N + col) = make_float2(c[2], c[3]);
            }
        }
    }
}

// ---------------- split helpers ----------------------------------------------
__device__ __forceinline__ void split_store_h(__half* hi, __half* lo, int i4, float4 v) {
    __half h0 = __float2half_rn(v.x);
    __half h1 = __float2half_rn(v.y);
    __half h2 = __float2half_rn(v.z);
    __half h3 = __float2half_rn(v.w);
    __half l0 = __float2half_rn(v.x - __half2float(h0));
    __half l1 = __float2half_rn(v.y - __half2float(h1));
    __half l2 = __float2half_rn(v.z - __half2float(h2));
    __half l3 = __float2half_rn(v.w - __half2float(h3));
    ((__half2*)hi)[2 * i4]     = __halves2half2(h0, h1);
    ((__half2*)hi)[2 * i4 + 1] = __halves2half2(h2, h3);
    ((__half2*)lo)[2 * i4]     = __halves2half2(l0, l1);
    ((__half2*)lo)[2 * i4 + 1] = __halves2half2(l2, l3);
}

// weights: fp32 -> fp16 (hi only)
__global__ void cvt_w_k(const float* __restrict__ x, __half* __restrict__ hi, int n4) {
    int i = blockIdx.x * 256 + threadIdx.x;
    if (i >= n4) return;
    float4 v = ((const float4*)x)[i];
    ((__half2*)hi)[2 * i]     = __halves2half2(__float2half_rn(v.x), __float2half_rn(v.y));
    ((__half2*)hi)[2 * i + 1] = __halves2half2(__float2half_rn(v.z), __float2half_rn(v.w));
}

// ---------------- rmsnorm (fused split output) --------------------------------
__global__ void rmsnorm_split_k(const float* __restrict__ x, const float* __restrict__ w,
                                float* __restrict__ y, __half* __restrict__ hi,
                                __half* __restrict__ lo) {
    int row = blockIdx.x;
    const float* xr = x + (size_t)row * CC;
    float* yr = y + (size_t)row * CC;
    float v[4];
    float ss = 0.f;
#pragma unroll
    for (int i = 0; i < 4; i++) {
        v[i] = xr[threadIdx.x + i * 256];
        ss += v[i] * v[i];
    }
#pragma unroll
    for (int off = 16; off; off >>= 1) ss += __shfl_xor_sync(0xffffffffu, ss, off);
    __shared__ float sred[8];
    __shared__ float stot;
    if ((threadIdx.x & 31) == 0) sred[threadIdx.x >> 5] = ss;
    __syncthreads();
    if (threadIdx.x < 8) {
        float t = sred[threadIdx.x];
#pragma unroll
        for (int off = 4; off; off >>= 1) t += __shfl_xor_sync(0xffu, t, off);
        if (threadIdx.x == 0) stot = t;
    }
    __syncthreads();
    float r = rsqrtf(stot / (float)CC + 1e-6f);
#pragma unroll
    for (int i = 0; i < 4; i++)
        yr[threadIdx.x + i * 256] = v[i] * r * w[threadIdx.x + i * 256];
    __syncthreads();
    float4 vv = ((const float4*)yr)[threadIdx.x];
    split_store_h(hi + (size_t)row * CC, lo + (size_t)row * CC, threadIdx.x, vv);
}

// ---------------- beta: fused dot + bias + sigmoid ---------------------------
__global__ __launch_bounds__(512)
void beta_k(const float* __restrict__ xn, const float* __restrict__ bw,
            const float* __restrict__ bias, float* __restrict__ beta) {
    __shared__ float xs[CC];
    const int row = blockIdx.x;
    for (int i = threadIdx.x; i < CC; i += 512) xs[i] = xn[(size_t)row * CC + i];
    __syncthreads();
    const int h = threadIdx.x >> 5;
    const int lane = threadIdx.x & 31;
    const float* w = bw + (size_t)h * CC;
    float acc = 0.f;
#pragma unroll 8
    for (int j = lane; j < CC; j += 32) acc += xs[j] * w[j];
#pragma unroll
    for (int off = 16; off; off >>= 1) acc += __shfl_xor_sync(0xffffffffu, acc, off);
    if (lane == 0) {
        float t = acc + bias[h];
        beta[(size_t)row * HH + h] = 1.f / (1.f + __expf(-t));
    }
}

// ---------------- elementwise helpers ----------------------------------------
__global__ void l2norm_k(float* __restrict__ x) {
    int vec = blockIdx.x * 8 + (threadIdx.x >> 5);
    int lane = threadIdx.x & 31;
    float* p = x + (size_t)vec * 64;
    float a = p[lane], b = p[lane + 32];
    float ss = a * a + b * b;
#pragma unroll
    for (int off = 16; off; off >>= 1) ss += __shfl_xor_sync(0xffffffffu, ss, off);
    float inv = 1.f / fmaxf(sqrtf(ss), 1e-12f);
    p[lane] = a * inv;
    p[lane + 32] = b * inv;
}

__global__ void gate_mul_split_k(const float* __restrict__ gate, const float* __restrict__ o,
                                 __half* __restrict__ hi, __half* __restrict__ lo) {
    int i = blockIdx.x * 256 + threadIdx.x;
    float4 gv = ((const float4*)gate)[i];
    float4 ov = ((const float4*)o)[i];
    float4 r;
    r.x = ov.x / (1.f + __expf(-gv.x));
    r.y = ov.y / (1.f + __expf(-gv.y));
    r.z = ov.z / (1.f + __expf(-gv.z));
    r.w = ov.w / (1.f + __expf(-gv.w));
    split_store_h(hi, lo, i, r);
}

__global__ void silu_mul_split_k(const float* __restrict__ g, const float* __restrict__ u,
                                 __half* __restrict__ hi, __half* __restrict__ lo) {
    int i = blockIdx.x * 256 + threadIdx.x;
    float4 gv = ((const float4*)g)[i];
    float4 uv = ((const float4*)u)[i];
    float4 r;
    r.x = (gv.x / (1.f + __expf(-gv.x))) * uv.x;
    r.y = (gv.y / (1.f + __expf(-gv.y))) * uv.y;
    r.z = (gv.z / (1.f + __expf(-gv.z))) * uv.z;
    r.w = (gv.w / (1.f + __expf(-gv.w))) * uv.w;
    split_store_h(hi, lo, i, r);
}

// ---------------- delta-rule scan --------------------------------------------
__global__ __launch_bounds__(128)
void delta_scan_k(const float* __restrict__ q, const float* __restrict__ k,
                  const float* __restrict__ v, const float* __restrict__ beta,
                  float* __restrict__ o) {
    const int b = blockIdx.x / HH;
    const int h = blockIdx.x % HH;
    const int tid = threadIdx.x;
    const int d = tid >> 1;
    const int s = tid & 1;
    const int cbase = s * 32;

    __shared__ float qs[2][64];
    __shared__ float ks[2][64];

    float Mrow[32];
#pragma unroll
    for (int j = 0; j < 32; j++) Mrow[j] = 0.f;

    const float* qb = q + (size_t)b * TT * CC + h * DD;
    const float* kb = k + (size_t)b * TT * CC + h * DD;
    const float* vb = v + (size_t)b * TT * CC + h * DD;
    const float* bb = beta + (size_t)b * TT * HH + h;
    float* ob = o + (size_t)b * TT * CC + h * DD;

    float rqk = (tid < 64) ? qb[tid] : kb[tid - 64];
    float rv = vb[d];
    float rb = bb[0];

    int buf = 0;
    for (int t = 0; t < TT; t++) {
        if (tid < 64) qs[buf][tid] = rqk; else ks[buf][tid - 64] = rqk;
        __syncthreads();
        float cv = rv, cb = rb;
        if (t + 1 < TT) {
            const int off = (t + 1) * CC;
            rqk = (tid < 64) ? qb[off + tid] : kb[off + tid - 64];
            rv = vb[off + d];
            rb = bb[(t + 1) * HH];
        }
        float po0 = 0.f, po1 = 0.f, pm0 = 0.f, pm1 = 0.f;
#pragma unroll
        for (int j = 0; j < 32; j += 2) {
            float q0 = qs[buf][cbase + j], q1 = qs[buf][cbase + j + 1];
            float k0 = ks[buf][cbase + j], k1 = ks[buf][cbase + j + 1];
            po0 += Mrow[j] * q0;
            po1 += Mrow[j + 1] * q1;
            pm0 += Mrow[j] * k0;
            pm1 += Mrow[j + 1] * k1;
        }
        float po = po0 + po1, pm = pm0 + pm1;
        po += __shfl_xor_sync(0xffffffffu, po, 1);
        pm += __shfl_xor_sync(0xffffffffu, pm, 1);
        float dvb = cb * (cv - pm);
#pragma unroll
        for (int j = 0; j < 32; j++) Mrow[j] += dvb * ks[buf][cbase + j];
        if (s == 0) ob[(size_t)t * CC + d] = po;
        buf ^= 1;
    }
}

// ---------------- launch ------------------------------------------------------
extern "C" void kernel_launch(void* const* d_in, const int* in_sizes, int n_in,
                              void* d_out, int out_size) {
    const float* x       = (const float*)d_in[0];
    const float* norm1_w = (const float*)d_in[3];
    const float* norm2_w = (const float*)d_in[4];
    const float* q_w     = (const float*)d_in[5];
    const float* k_w     = (const float*)d_in[6];
    const float* v_w     = (const float*)d_in[7];
    const float* beta_w  = (const float*)d_in[8];
    const float* beta_b  = (const float*)d_in[9];
    const float* gate_w  = (const float*)d_in[10];
    const float* o_w     = (const float*)d_in[11];
    const float* fg_w    = (const float*)d_in[12];
    const float* fu_w    = (const float*)d_in[13];
    const float* fd_w    = (const float*)d_in[14];
    float* out = (float*)d_out;

    float *xn, *q, *k, *v, *gate, *o, *x1, *beta, *gg, *uu;
    __half *ah, *al, *wh;
    cudaGetSymbolAddress((void**)&xn,   g_xn);
    cudaGetSymbolAddress((void**)&q,    g_q);
    cudaGetSymbolAddress((void**)&k,    g_k);
    cudaGetSymbolAddress((void**)&v,    g_v);
    cudaGetSymbolAddress((void**)&gate, g_gate);
    cudaGetSymbolAddress((void**)&o,    g_o);
    cudaGetSymbolAddress((void**)&x1,   g_x1);
    cudaGetSymbolAddress((void**)&beta, g_beta);
    cudaGetSymbolAddress((void**)&gg,   g_gg);
    cudaGetSymbolAddress((void**)&uu,   g_uu);
    cudaGetSymbolAddress((void**)&ah,   g_a_hi);
    cudaGetSymbolAddress((void**)&al,   g_a_lo);
    cudaGetSymbolAddress((void**)&wh,   g_w_hi);

    cudaFuncSetAttribute(gemm_mma, cudaFuncAttributeMaxDynamicSharedMemorySize,
                         GSMEM_TOTAL);

    auto cvtw = [&](const float* src, int n) {
        cvt_w_k<<<(n / 4 + 255) / 256, 256>>>(src, wh, n / 4);
    };
    auto gemm = [&](float* Cm, const float* R, int N, int K) {
        gemm_mma<<<dim3(N / TILE_MN, MROWS / TILE_MN), 256, GSMEM_TOTAL>>>(
            Cm, R, ah, al, wh, MROWS, N, K);
    };

    // ---- attention branch ----
    rmsnorm_split_k<<<MROWS, 256>>>(x, norm1_w, xn, ah, al);
    cvtw(q_w, CC * CC);    gemm(q,    nullptr, CC, CC);
    cvtw(k_w, CC * CC);    gemm(k,    nullptr, CC, CC);
    cvtw(v_w, CC * CC);    gemm(v,    nullptr, CC, CC);
    cvtw(gate_w, CC * CC); gemm(gate, nullptr, CC, CC);
    beta_k<<<MROWS, 512>>>(xn, beta_w, beta_b, beta);
    l2norm_k<<<(MROWS * HH) / 8, 256>>>(q);
    l2norm_k<<<(MROWS * HH) / 8, 256>>>(k);
    delta_scan_k<<<BB * HH, 128>>>(q, k, v, beta, o);
    gate_mul_split_k<<<MROWS * CC / 4 / 256, 256>>>(gate, o, ah, al);
    cvtw(o_w, CC * CC);    gemm(x1, x, CC, CC);        // x1 = x + attn_out
    // ---- FFN branch ----
    rmsnorm_split_k<<<MROWS, 256>>>(x1, norm2_w, xn, ah, al);
    cvtw(fg_w, FF * CC);   gemm(gg, nullptr, FF, CC);
    cvtw(fu_w, FF * CC);   gemm(uu, nullptr, FF, CC);
    silu_mul_split_k<<<MROWS * FF / 4 / 256, 256>>>(gg, uu, ah, al);
    cvtw(fd_w, CC * FF);   gemm(out, x1, CC, FF);      // out = x1 + ffn_out
}

// round 9
// speedup vs baseline: 1.3746x; 1.0793x over previous
#include <cuda_runtime.h>
#include <cuda_fp16.h>
#include <cstdint>
#include <math.h>

#define BB 4
#define TT 2048
#define CC 1024
#define HH 16
#define DD 64
#define FF 4096
#define MROWS (BB*TT)   // 8192

// ---------------- scratch (static device globals; no allocation) -------------
__device__ float g_xn[MROWS*CC];
__device__ float g_q[MROWS*CC];
__device__ float g_k[MROWS*CC];
__device__ float g_v[MROWS*CC];
__device__ float g_gate[MROWS*CC];
__device__ float g_o[MROWS*CC];
__device__ float g_x1[MROWS*CC];
__device__ float g_beta[MROWS*HH];
__device__ float g_gg[MROWS*FF];
__device__ float g_uu[MROWS*FF];
// fp16 buffers
__device__ __align__(16) __half g_a_hi[MROWS*FF];
__device__ __align__(16) __half g_a_lo[MROWS*FF];
__device__ __align__(16) __half g_w_hi[FF*CC];

// ================= PTX helpers (sm_80-era, plain-target safe) ================
__device__ __forceinline__ uint32_t smem_u32(const void* p) {
    return (uint32_t)__cvta_generic_to_shared(p);
}
__device__ __forceinline__ void cp16(uint32_t dst, const void* src) {
    asm volatile("cp.async.cg.shared.global [%0], [%1], 16;\n" :: "r"(dst), "l"(src));
}
__device__ __forceinline__ void cp_commit() {
    asm volatile("cp.async.commit_group;\n" ::: "memory");
}
__device__ __forceinline__ void ldsm4(uint32_t* d, uint32_t addr) {
    asm volatile("ldmatrix.sync.aligned.m8n8.x4.shared.b16 {%0,%1,%2,%3}, [%4];"
                 : "=r"(d[0]), "=r"(d[1]), "=r"(d[2]), "=r"(d[3]) : "r"(addr));
}
__device__ __forceinline__ void mma_fp16(float* c, const uint32_t* a,
                                         uint32_t b0, uint32_t b1) {
    asm volatile(
        "mma.sync.aligned.m16n8k16.row.col.f32.f16.f16.f32 "
        "{%0,%1,%2,%3}, {%4,%5,%6,%7}, {%8,%9}, {%0,%1,%2,%3};"
        : "+f"(c[0]), "+f"(c[1]), "+f"(c[2]), "+f"(c[3])
        : "r"(a[0]), "r"(a[1]), "r"(a[2]), "r"(a[3]), "r"(b0), "r"(b1));
}

// ================= split-fp16 GEMM via mma.sync ==============================
// C[M,N] = (Ah+Al)[M,K] * Bh[N,K]^T (+ optional residual R), fp32 out.
// 2 passes: Ah*Bh + Al*Bh.
// CTA 128x256, 512 threads (16 warps = 4/SMSP to feed the HMMA pipe),
// warp tile 32x64, KT=64, 2 stages (128KB smem), 1 CTA/SM, no spills.
#define TILE_M 128
#define TILE_N 256
#define KT 64
#define SUB_BYTES (128*128)          // 16KB: 128 rows x 128B
#define OFF_A_HI 0
#define OFF_A_LO (SUB_BYTES)
#define OFF_B    (2*SUB_BYTES)       // B: 256 rows x 128B = 32KB
#define STAGE_BYTES (4*SUB_BYTES)    // 64KB
#define GSMEM_TOTAL (2*STAGE_BYTES)  // 128KB
#define GTHREADS 512

__device__ __forceinline__ void load_tile(const __half* __restrict__ g, int ldk,
                                          int row0, int k0, uint32_t dstbase,
                                          int rows, int tid) {
#pragma unroll
    for (int i = tid; i < rows * 8; i += GTHREADS) {
        int r = i >> 3;
        int c16 = i & 7;
        const __half* src = g + (size_t)(row0 + r) * ldk + k0 + c16 * 8;
        uint32_t dst = dstbase + r * 128 + (((uint32_t)(c16 ^ (r & 7))) << 4);
        cp16(dst, src);
    }
}

__global__ __launch_bounds__(GTHREADS, 1)
void gemm_mma(float* __restrict__ C, const float* __restrict__ R,
              const __half* __restrict__ Ah, const __half* __restrict__ Al,
              const __half* __restrict__ Bh, int M, int N, int K) {
    extern __shared__ __align__(1024) char smem[];
    const uint32_t sbase = smem_u32(smem);
    const int tid = threadIdx.x;
    const int wid = tid >> 5;
    const int lane = tid & 31;
    const int wm = wid & 3;          // 4 m-groups of 32 rows
    const int wn = wid >> 2;         // 4 n-groups of 64 cols
    const int bm = blockIdx.y * TILE_M;
    const int bn = blockIdx.x * TILE_N;

    const int mi = lane >> 3;
    const int lr = lane & 7;
    const uint32_t a_off = (uint32_t)(wm * 32 + ((mi & 1) << 3) + lr) * 128;
    const uint32_t a_cb = (uint32_t)(mi >> 1);
    const uint32_t b_off = (uint32_t)(wn * 64 + ((mi >> 1) << 3) + lr) * 128;
    const uint32_t b_cb = (uint32_t)(mi & 1);

    float acc[2][8][4];
#pragma unroll
    for (int a = 0; a < 2; a++)
#pragma unroll
        for (int b = 0; b < 8; b++)
#pragma unroll
            for (int c = 0; c < 4; c++) acc[a][b][c] = 0.f;

    const int NC = K / KT;

    load_tile(Ah, K, bm, 0, sbase + OFF_A_HI, 128, tid);
    load_tile(Al, K, bm, 0, sbase + OFF_A_LO, 128, tid);
    load_tile(Bh, K, bn, 0, sbase + OFF_B, 256, tid);
    cp_commit();
    load_tile(Ah, K, bm, KT, sbase + STAGE_BYTES + OFF_A_HI, 128, tid);
    load_tile(Al, K, bm, KT, sbase + STAGE_BYTES + OFF_A_LO, 128, tid);
    load_tile(Bh, K, bn, KT, sbase + STAGE_BYTES + OFF_B, 256, tid);
    cp_commit();

    for (int kc = 0; kc < NC; kc++) {
        const uint32_t sb = sbase + (uint32_t)(kc & 1) * STAGE_BYTES;
        if (kc + 2 < NC) {
            asm volatile("cp.async.wait_group 1;\n" ::: "memory");
        } else {
            asm volatile("cp.async.wait_group 0;\n" ::: "memory");
        }
        __syncthreads();

#pragma unroll
        for (int ki = 0; ki < 4; ki++) {
            uint32_t ah[2][4], al2[2][4], bh[4][4];
            const uint32_t ax = ((uint32_t)(ki * 2) + a_cb) ^ (uint32_t)lr;
            const uint32_t bx = ((uint32_t)(ki * 2) + b_cb) ^ (uint32_t)lr;
#pragma unroll
            for (int mt = 0; mt < 2; mt++) {
                uint32_t aaddr = sb + a_off + (uint32_t)(mt * 2048) + (ax << 4);
                ldsm4(ah[mt], aaddr + OFF_A_HI);
                ldsm4(al2[mt], aaddr + OFF_A_LO);
            }
#pragma unroll
            for (int nt = 0; nt < 4; nt++) {
                uint32_t baddr = sb + OFF_B + b_off + (uint32_t)(nt * 2048) + (bx << 4);
                ldsm4(bh[nt], baddr);
            }
            // 2 separated passes; 16 independent accumulators per pass
#pragma unroll
            for (int sp = 0; sp < 2; sp++) {
#pragma unroll
                for (int mt = 0; mt < 2; mt++)
#pragma unroll
                    for (int nt = 0; nt < 4; nt++)
#pragma unroll
                        for (int h = 0; h < 2; h++) {
                            const uint32_t* a = (sp == 1) ? al2[mt] : ah[mt];
                            mma_fp16(acc[mt][nt * 2 + h], a,
                                     bh[nt][2 * h], bh[nt][2 * h + 1]);
                        }
            }
        }
        __syncthreads();
        if (kc + 2 < NC) {
            const uint32_t pb = sbase + (uint32_t)(kc & 1) * STAGE_BYTES;
            const int k0 = (kc + 2) * KT;
            load_tile(Ah, K, bm, k0, pb + OFF_A_HI, 128, tid);
            load_tile(Al, K, bm, k0, pb + OFF_A_LO, 128, tid);
            load_tile(Bh, K, bn, k0, pb + OFF_B, 256, tid);
            cp_commit();
        }
    }

    const int g = lane >> 2;
    const int t = lane & 3;
#pragma unroll
    for (int mt = 0; mt < 2; mt++) {
        const int row0 = bm + wm * 32 + mt * 16 + g;
#pragma unroll
        for (int n8 = 0; n8 < 8; n8++) {
            const int col = bn + wn * 64 + n8 * 8 + t * 2;
            float* c = acc[mt][n8];
            if (R) {
                const float* r0 = R + (size_t)row0 * N + col;
                const float* r1 = R + (size_t)(row0 + 8) * N + col;
                *(float2*)(C + (size_t)row0 * N + col) =
                    make_float2(c[0] + r0[0], c[1] + r0[1]);
                *(float2*)(C + (size_t)(row0 + 8) * N + col) =
                    make_float2(c[2] + r1[0], c[3] + r1[1]);
            } else {
                *(float2*)(C + (size_t)row0 * N + col)       = make_float2(c[0], c[1]);
                *(float2*)(C + (size_t)(row0 + 8) * N + col) = make_float2(c[2], c[3]);
            }
        }
    }
}

// ---------------- split helpers ----------------------------------------------
__device__ __forceinline__ void split_store_h(__half* hi, __half* lo, int i4, float4 v) {
    __half h0 = __float2half_rn(v.x);
    __half h1 = __float2half_rn(v.y);
    __half h2 = __float2half_rn(v.z);
    __half h3 = __float2half_rn(v.w);
    __half l0 = __float2half_rn(v.x - __half2float(h0));
    __half l1 = __float2half_rn(v.y - __half2float(h1));
    __half l2 = __float2half_rn(v.z - __half2float(h2));
    __half l3 = __float2half_rn(v.w - __half2float(h3));
    ((__half2*)hi)[2 * i4]     = __halves2half2(h0, h1);
    ((__half2*)hi)[2 * i4 + 1] = __halves2half2(h2, h3);
    ((__half2*)lo)[2 * i4]     = __halves2half2(l0, l1);
    ((__half2*)lo)[2 * i4 + 1] = __halves2half2(l2, l3);
}

// weights: fp32 -> fp16 (hi only)
__global__ void cvt_w_k(const float* __restrict__ x, __half* __restrict__ hi, int n4) {
    int i = blockIdx.x * 256 + threadIdx.x;
    if (i >= n4) return;
    float4 v = ((const float4*)x)[i];
    ((__half2*)hi)[2 * i]     = __halves2half2(__float2half_rn(v.x), __float2half_rn(v.y));
    ((__half2*)hi)[2 * i + 1] = __halves2half2(__float2half_rn(v.z), __float2half_rn(v.w));
}

// ---------------- rmsnorm (fused split output) --------------------------------
__global__ void rmsnorm_split_k(const float* __restrict__ x, const float* __restrict__ w,
                                float* __restrict__ y, __half* __restrict__ hi,
                                __half* __restrict__ lo) {
    int row = blockIdx.x;
    const float* xr = x + (size_t)row * CC;
    float* yr = y + (size_t)row * CC;
    float v[4];
    float ss = 0.f;
#pragma unroll
    for (int i = 0; i < 4; i++) {
        v[i] = xr[threadIdx.x + i * 256];
        ss += v[i] * v[i];
    }
#pragma unroll
    for (int off = 16; off; off >>= 1) ss += __shfl_xor_sync(0xffffffffu, ss, off);
    __shared__ float sred[8];
    __shared__ float stot;
    if ((threadIdx.x & 31) == 0) sred[threadIdx.x >> 5] = ss;
    __syncthreads();
    if (threadIdx.x < 8) {
        float t = sred[threadIdx.x];
#pragma unroll
        for (int off = 4; off; off >>= 1) t += __shfl_xor_sync(0xffu, t, off);
        if (threadIdx.x == 0) stot = t;
    }
    __syncthreads();
    float r = rsqrtf(stot / (float)CC + 1e-6f);
#pragma unroll
    for (int i = 0; i < 4; i++)
        yr[threadIdx.x + i * 256] = v[i] * r * w[threadIdx.x + i * 256];
    __syncthreads();
    float4 vv = ((const float4*)yr)[threadIdx.x];
    split_store_h(hi + (size_t)row * CC, lo + (size_t)row * CC, threadIdx.x, vv);
}

// ---------------- beta: fused dot + bias + sigmoid ---------------------------
__global__ __launch_bounds__(512)
void beta_k(const float* __restrict__ xn, const float* __restrict__ bw,
            const float* __restrict__ bias, float* __restrict__ beta) {
    __shared__ float xs[CC];
    const int row = blockIdx.x;
    for (int i = threadIdx.x; i < CC; i += 512) xs[i] = xn[(size_t)row * CC + i];
    __syncthreads();
    const int h = threadIdx.x >> 5;
    const int lane = threadIdx.x & 31;
    const float* w = bw + (size_t)h * CC;
    float acc = 0.f;
#pragma unroll 8
    for (int j = lane; j < CC; j += 32) acc += xs[j] * w[j];
#pragma unroll
    for (int off = 16; off; off >>= 1) acc += __shfl_xor_sync(0xffffffffu, acc, off);
    if (lane == 0) {
        float t = acc + bias[h];
        beta[(size_t)row * HH + h] = 1.f / (1.f + __expf(-t));
    }
}

// ---------------- elementwise helpers ----------------------------------------
__global__ void l2norm_k(float* __restrict__ x) {
    int vec = blockIdx.x * 8 + (threadIdx.x >> 5);
    int lane = threadIdx.x & 31;
    float* p = x + (size_t)vec * 64;
    float a = p[lane], b = p[lane + 32];
    float ss = a * a + b * b;
#pragma unroll
    for (int off = 16; off; off >>= 1) ss += __shfl_xor_sync(0xffffffffu, ss, off);
    float inv = 1.f / fmaxf(sqrtf(ss), 1e-12f);
    p[lane] = a * inv;
    p[lane + 32] = b * inv;
}

__global__ void gate_mul_split_k(const float* __restrict__ gate, const float* __restrict__ o,
                                 __half* __restrict__ hi, __half* __restrict__ lo) {
    int i = blockIdx.x * 256 + threadIdx.x;
    float4 gv = ((const float4*)gate)[i];
    float4 ov = ((const float4*)o)[i];
    float4 r;
    r.x = ov.x / (1.f + __expf(-gv.x));
    r.y = ov.y / (1.f + __expf(-gv.y));
    r.z = ov.z / (1.f + __expf(-gv.z));
    r.w = ov.w / (1.f + __expf(-gv.w));
    split_store_h(hi, lo, i, r);
}

__global__ void silu_mul_split_k(const float* __restrict__ g, const float* __restrict__ u,
                                 __half* __restrict__ hi, __half* __restrict__ lo) {
    int i = blockIdx.x * 256 + threadIdx.x;
    float4 gv = ((const float4*)g)[i];
    float4 uv = ((const float4*)u)[i];
    float4 r;
    r.x = (gv.x / (1.f + __expf(-gv.x))) * uv.x;
    r.y = (gv.y / (1.f + __expf(-gv.y))) * uv.y;
    r.z = (gv.z / (1.f + __expf(-gv.z))) * uv.z;
    r.w = (gv.w / (1.f + __expf(-gv.w))) * uv.w;
    split_store_h(hi, lo, i, r);
}

// ---------------- delta-rule scan --------------------------------------------
__global__ __launch_bounds__(128)
void delta_scan_k(const float* __restrict__ q, const float* __restrict__ k,
                  const float* __restrict__ v, const float* __restrict__ beta,
                  float* __restrict__ o) {
    const int b = blockIdx.x / HH;
    const int h = blockIdx.x % HH;
    const int tid = threadIdx.x;
    const int d = tid >> 1;
    const int s = tid & 1;
    const int cbase = s * 32;

    __shared__ float qs[2][64];
    __shared__ float ks[2][64];

    float Mrow[32];
#pragma unroll
    for (int j = 0; j < 32; j++) Mrow[j] = 0.f;

    const float* qb = q + (size_t)b * TT * CC + h * DD;
    const float* kb = k + (size_t)b * TT * CC + h * DD;
    const float* vb = v + (size_t)b * TT * CC + h * DD;
    const float* bb = beta + (size_t)b * TT * HH + h;
    float* ob = o + (size_t)b * TT * CC + h * DD;

    float rqk = (tid < 64) ? qb[tid] : kb[tid - 64];
    float rv = vb[d];
    float rb = bb[0];

    int buf = 0;
    for (int t = 0; t < TT; t++) {
        if (tid < 64) qs[buf][tid] = rqk; else ks[buf][tid - 64] = rqk;
        __syncthreads();
        float cv = rv, cb = rb;
        if (t + 1 < TT) {
            const int off = (t + 1) * CC;
            rqk = (tid < 64) ? qb[off + tid] : kb[off + tid - 64];
            rv = vb[off + d];
            rb = bb[(t + 1) * HH];
        }
        float po0 = 0.f, po1 = 0.f, pm0 = 0.f, pm1 = 0.f;
#pragma unroll
        for (int j = 0; j < 32; j += 2) {
            float q0 = qs[buf][cbase + j], q1 = qs[buf][cbase + j + 1];
            float k0 = ks[buf][cbase + j], k1 = ks[buf][cbase + j + 1];
            po0 += Mrow[j] * q0;
            po1 += Mrow[j + 1] * q1;
            pm0 += Mrow[j] * k0;
            pm1 += Mrow[j + 1] * k1;
        }
        float po = po0 + po1, pm = pm0 + pm1;
        po += __shfl_xor_sync(0xffffffffu, po, 1);
        pm += __shfl_xor_sync(0xffffffffu, pm, 1);
        float dvb = cb * (cv - pm);
#pragma unroll
        for (int j = 0; j < 32; j++) Mrow[j] += dvb * ks[buf][cbase + j];
        if (s == 0) ob[(size_t)t * CC + d] = po;
        buf ^= 1;
    }
}

// ---------------- launch ------------------------------------------------------
extern "C" void kernel_launch(void* const* d_in, const int* in_sizes, int n_in,
                              void* d_out, int out_size) {
    const float* x       = (const float*)d_in[0];
    const float* norm1_w = (const float*)d_in[3];
    const float* norm2_w = (const float*)d_in[4];
    const float* q_w     = (const float*)d_in[5];
    const float* k_w     = (const float*)d_in[6];
    const float* v_w     = (const float*)d_in[7];
    const float* beta_w  = (const float*)d_in[8];
    const float* beta_b  = (const float*)d_in[9];
    const float* gate_w  = (const float*)d_in[10];
    const float* o_w     = (const float*)d_in[11];
    const float* fg_w    = (const float*)d_in[12];
    const float* fu_w    = (const float*)d_in[13];
    const float* fd_w    = (const float*)d_in[14];
    float* out = (float*)d_out;

    float *xn, *q, *k, *v, *gate, *o, *x1, *beta, *gg, *uu;
    __half *ah, *al, *wh;
    cudaGetSymbolAddress((void**)&xn,   g_xn);
    cudaGetSymbolAddress((void**)&q,    g_q);
    cudaGetSymbolAddress((void**)&k,    g_k);
    cudaGetSymbolAddress((void**)&v,    g_v);
    cudaGetSymbolAddress((void**)&gate, g_gate);
    cudaGetSymbolAddress((void**)&o,    g_o);
    cudaGetSymbolAddress((void**)&x1,   g_x1);
    cudaGetSymbolAddress((void**)&beta, g_beta);
    cudaGetSymbolAddress((void**)&gg,   g_gg);
    cudaGetSymbolAddress((void**)&uu,   g_uu);
    cudaGetSymbolAddress((void**)&ah,   g_a_hi);
    cudaGetSymbolAddress((void**)&al,   g_a_lo);
    cudaGetSymbolAddress((void**)&wh,   g_w_hi);

    cudaFuncSetAttribute(gemm_mma, cudaFuncAttributeMaxDynamicSharedMemorySize,
                         GSMEM_TOTAL);

    auto cvtw = [&](const float* src, int n) {
        cvt_w_k<<<(n / 4 + 255) / 256, 256>>>(src, wh, n / 4);
    };
    auto gemm = [&](float* Cm, const float* R, int N, int K) {
        gemm_mma<<<dim3(N / TILE_N, MROWS / TILE_M), GTHREADS, GSMEM_TOTAL>>>(
            Cm, R, ah, al, wh, MROWS, N, K);
    };

    // ---- attention branch ----
    rmsnorm_split_k<<<MROWS, 256>>>(x, norm1_w, xn, ah, al);
    cvtw(q_w, CC * CC);    gemm(q,    nullptr, CC, CC);
    cvtw(k_w, CC * CC);    gemm(k,    nullptr, CC, CC);
    cvtw(v_w, CC * CC);    gemm(v,    nullptr, CC, CC);
    cvtw(gate_w, CC * CC); gemm(gate, nullptr, CC, CC);
    beta_k<<<MROWS, 512>>>(xn, beta_w, beta_b, beta);
    l2norm_k<<<(MROWS * HH) / 8, 256>>>(q);
    l2norm_k<<<(MROWS * HH) / 8, 256>>>(k);
    delta_scan_k<<<BB * HH, 128>>>(q, k, v, beta, o);
    gate_mul_split_k<<<MROWS * CC / 4 / 256, 256>>>(gate, o, ah, al);
    cvtw(o_w, CC * CC);    gemm(x1, x, CC, CC);        // x1 = x + attn_out
    // ---- FFN branch ----
    rmsnorm_split_k<<<MROWS, 256>>>(x1, norm2_w, xn, ah, al);
    cvtw(fg_w, FF * CC);   gemm(gg, nullptr, FF, CC);
    cvtw(fu_w, FF * CC);   gemm(uu, nullptr, FF, CC);
    silu_mul_split_k<<<MROWS * FF / 4 / 256, 256>>>(gg, uu, ah, al);
    cvtw(fd_w, CC * FF);   gemm(out, x1, CC, FF);      // out = x1 + ffn_out
}

// round 12
// speedup vs baseline: 1.4290x; 1.0396x over previous
#include <cuda_runtime.h>
#include <cuda_fp16.h>
#include <cstdint>
#include <math.h>

#define BB 4
#define TT 2048
#define CC 1024
#define HH 16
#define DD 64
#define FF 4096
#define MROWS (BB*TT)   // 8192

// ---------------- scratch (static device globals; no allocation) -------------
__device__ float g_xn[MROWS*CC];
__device__ float g_o[MROWS*CC];
__device__ float g_x1[MROWS*CC];
__device__ float g_beta[MROWS*HH];
__device__ float g_ff[MROWS*2*FF];              // QKVG out (ld 4096) / FFN out (ld 8192)
__device__ __align__(16) __half g_a_hi[MROWS*FF];
__device__ __align__(16) __half g_a_lo[MROWS*FF];
__device__ __align__(16) __half g_w_hi[2*FF*CC];

// ================= PTX helpers (sm_80-era, plain-target safe) ================
__device__ __forceinline__ uint32_t smem_u32(const void* p) {
    return (uint32_t)__cvta_generic_to_shared(p);
}
__device__ __forceinline__ void cp16(uint32_t dst, const void* src) {
    asm volatile("cp.async.cg.shared.global [%0], [%1], 16;\n" :: "r"(dst), "l"(src));
}
__device__ __forceinline__ void cp_commit() {
    asm volatile("cp.async.commit_group;\n" ::: "memory");
}
__device__ __forceinline__ void ldsm4(uint32_t* d, uint32_t addr) {
    asm volatile("ldmatrix.sync.aligned.m8n8.x4.shared.b16 {%0,%1,%2,%3}, [%4];"
                 : "=r"(d[0]), "=r"(d[1]), "=r"(d[2]), "=r"(d[3]) : "r"(addr));
}
__device__ __forceinline__ void mma_fp16(float* c, const uint32_t* a,
                                         uint32_t b0, uint32_t b1) {
    asm volatile(
        "mma.sync.aligned.m16n8k16.row.col.f32.f16.f16.f32 "
        "{%0,%1,%2,%3}, {%4,%5,%6,%7}, {%8,%9}, {%0,%1,%2,%3};"
        : "+f"(c[0]), "+f"(c[1]), "+f"(c[2]), "+f"(c[3])
        : "r"(a[0]), "r"(a[1]), "r"(a[2]), "r"(a[3]), "r"(b0), "r"(b1));
}

// ================= split-fp16 GEMM via mma.sync ==============================
// C[M,N] = (Ah+Al)[M,K] * Bh[N,K]^T (+ optional residual R), fp32 out.
// CTA 128x256, 512 threads, warp tile 32x64, KT=64.
// 3 smem stages (192KB), prefetch distance 2 => single __syncthreads per chunk
// (the fill buffer is never the read buffer), cp.async overlaps MMA.
#define TILE_M 128
#define TILE_N 256
#define KT 64
#define SUB_BYTES (128*128)          // 16KB: 128 rows x 128B
#define OFF_A_HI 0
#define OFF_A_LO (SUB_BYTES)
#define OFF_B    (2*SUB_BYTES)       // B: 256 rows x 128B = 32KB
#define STAGE_BYTES (4*SUB_BYTES)    // 64KB
#define GSMEM_TOTAL (3*STAGE_BYTES)  // 192KB
#define GTHREADS 512

__device__ __forceinline__ void load_tile(const __half* __restrict__ g, int ldk,
                                          int row0, int k0, uint32_t dstbase,
                                          int rows, int tid) {
#pragma unroll
    for (int i = tid; i < rows * 8; i += GTHREADS) {
        int r = i >> 3;
        int c16 = i & 7;
        const __half* src = g + (size_t)(row0 + r) * ldk + k0 + c16 * 8;
        uint32_t dst = dstbase + r * 128 + (((uint32_t)(c16 ^ (r & 7))) << 4);
        cp16(dst, src);
    }
}

__device__ __forceinline__ void load_stage(const __half* Ah, const __half* Al,
                                           const __half* Bh, int K, int bm, int bn,
                                           int k0, uint32_t sb, int tid) {
    load_tile(Ah, K, bm, k0, sb + OFF_A_HI, 128, tid);
    load_tile(Al, K, bm, k0, sb + OFF_A_LO, 128, tid);
    load_tile(Bh, K, bn, k0, sb + OFF_B, 256, tid);
    cp_commit();
}

__global__ __launch_bounds__(GTHREADS, 1)
void gemm_mma(float* __restrict__ C, const float* __restrict__ R,
              const __half* __restrict__ Ah, const __half* __restrict__ Al,
              const __half* __restrict__ Bh, int M, int N, int K) {
    extern __shared__ __align__(1024) char smem[];
    const uint32_t sbase = smem_u32(smem);
    const int tid = threadIdx.x;
    const int wid = tid >> 5;
    const int lane = tid & 31;
    const int wm = wid & 3;
    const int wn = wid >> 2;
    const int bm = blockIdx.y * TILE_M;
    const int bn = blockIdx.x * TILE_N;

    const int mi = lane >> 3;
    const int lr = lane & 7;
    const uint32_t a_off = (uint32_t)(wm * 32 + ((mi & 1) << 3) + lr) * 128;
    const uint32_t a_cb = (uint32_t)(mi >> 1);
    const uint32_t b_off = (uint32_t)(wn * 64 + ((mi >> 1) << 3) + lr) * 128;
    const uint32_t b_cb = (uint32_t)(mi & 1);

    float acc[2][8][4];
#pragma unroll
    for (int a = 0; a < 2; a++)
#pragma unroll
        for (int b = 0; b < 8; b++)
#pragma unroll
            for (int c = 0; c < 4; c++) acc[a][b][c] = 0.f;

    const int NC = K / KT;

    load_stage(Ah, Al, Bh, K, bm, bn, 0, sbase, tid);
    load_stage(Ah, Al, Bh, K, bm, bn, KT, sbase + STAGE_BYTES, tid);

    for (int kc = 0; kc < NC; kc++) {
        if (kc + 1 < NC) {
            asm volatile("cp.async.wait_group 1;\n" ::: "memory");
        } else {
            asm volatile("cp.async.wait_group 0;\n" ::: "memory");
        }
        __syncthreads();
        if (kc + 2 < NC) {
            load_stage(Ah, Al, Bh, K, bm, bn, (kc + 2) * KT,
                       sbase + (uint32_t)((kc + 2) % 3) * STAGE_BYTES, tid);
        }
        const uint32_t sb = sbase + (uint32_t)(kc % 3) * STAGE_BYTES;

#pragma unroll
        for (int ki = 0; ki < 4; ki++) {
            uint32_t ah[2][4], al2[2][4], bh[4][4];
            const uint32_t ax = ((uint32_t)(ki * 2) + a_cb) ^ (uint32_t)lr;
            const uint32_t bx = ((uint32_t)(ki * 2) + b_cb) ^ (uint32_t)lr;
#pragma unroll
            for (int mt = 0; mt < 2; mt++) {
                uint32_t aaddr = sb + a_off + (uint32_t)(mt * 2048) + (ax << 4);
                ldsm4(ah[mt], aaddr + OFF_A_HI);
                ldsm4(al2[mt], aaddr + OFF_A_LO);
            }
#pragma unroll
            for (int nt = 0; nt < 4; nt++) {
                uint32_t baddr = sb + OFF_B + b_off + (uint32_t)(nt * 2048) + (bx << 4);
                ldsm4(bh[nt], baddr);
            }
#pragma unroll
            for (int sp = 0; sp < 2; sp++) {
#pragma unroll
                for (int mt = 0; mt < 2; mt++)
#pragma unroll
                    for (int nt = 0; nt < 4; nt++)
#pragma unroll
                        for (int h = 0; h < 2; h++) {
                            const uint32_t* a = (sp == 1) ? al2[mt] : ah[mt];
                            mma_fp16(acc[mt][nt * 2 + h], a,
                                     bh[nt][2 * h], bh[nt][2 * h + 1]);
                        }
            }
        }
    }

    const int g = lane >> 2;
    const int t = lane & 3;
#pragma unroll
    for (int mt = 0; mt < 2; mt++) {
        const int row0 = bm + wm * 32 + mt * 16 + g;
#pragma unroll
        for (int n8 = 0; n8 < 8; n8++) {
            const int col = bn + wn * 64 + n8 * 8 + t * 2;
            float* c = acc[mt][n8];
            if (R) {
                const float* r0 = R + (size_t)row0 * N + col;
                const float* r1 = R + (size_t)(row0 + 8) * N + col;
                *(float2*)(C + (size_t)row0 * N + col) =
                    make_float2(c[0] + r0[0], c[1] + r0[1]);
                *(float2*)(C + (size_t)(row0 + 8) * N + col) =
                    make_float2(c[2] + r1[0], c[3] + r1[1]);
            } else {
                *(float2*)(C + (size_t)row0 * N + col)       = make_float2(c[0], c[1]);
                *(float2*)(C + (size_t)(row0 + 8) * N + col) = make_float2(c[2], c[3]);
            }
        }
    }
}

// ---------------- split helpers ----------------------------------------------
__device__ __forceinline__ void split_store_h(__half* hi, __half* lo, int i4, float4 v) {
    __half h0 = __float2half_rn(v.x);
    __half h1 = __float2half_rn(v.y);
    __half h2 = __float2half_rn(v.z);
    __half h3 = __float2half_rn(v.w);
    __half l0 = __float2half_rn(v.x - __half2float(h0));
    __half l1 = __float2half_rn(v.y - __half2float(h1));
    __half l2 = __float2half_rn(v.z - __half2float(h2));
    __half l3 = __float2half_rn(v.w - __half2float(h3));
    ((__half2*)hi)[2 * i4]     = __halves2half2(h0, h1);
    ((__half2*)hi)[2 * i4 + 1] = __halves2half2(h2, h3);
    ((__half2*)lo)[2 * i4]     = __halves2half2(l0, l1);
    ((__half2*)lo)[2 * i4 + 1] = __halves2half2(l2, l3);
}

// weights: fp32 -> fp16
__global__ void cvt_w_k(const float* __restrict__ x, __half* __restrict__ hi, int n4) {
    int i = blockIdx.x * 256 + threadIdx.x;
    if (i >= n4) return;
    float4 v = ((const float4*)x)[i];
    ((__half2*)hi)[2 * i]     = __halves2half2(__float2half_rn(v.x), __float2half_rn(v.y));
    ((__half2*)hi)[2 * i + 1] = __halves2half2(__float2half_rn(v.z), __float2half_rn(v.w));
}

// merged q/k/v/gate weight convert -> wh rows [0,4C)
__global__ void cvt_qkvg_k(const float* __restrict__ qw, const float* __restrict__ kw,
                           const float* __restrict__ vw, const float* __restrict__ gw,
                           __half* __restrict__ hi) {
    int i = blockIdx.x * 256 + threadIdx.x;        // over 4 * CC*CC/4 float4s
    int region = i >> 18;                          // CC*CC/4 = 262144
    int j = i & 0x3FFFF;
    const float* src = (region == 0) ? qw : (region == 1) ? kw : (region == 2) ? vw : gw;
    float4 v = ((const float4*)src)[j];
    __half* dst = hi + ((size_t)region << 20);     // CC*CC halves per region
    ((__half2*)dst)[2 * j]     = __halves2half2(__float2half_rn(v.x), __float2half_rn(v.y));
    ((__half2*)dst)[2 * j + 1] = __halves2half2(__float2half_rn(v.z), __float2half_rn(v.w));
}

// ---------------- rmsnorm (fused split output) --------------------------------
__global__ void rmsnorm_split_k(const float* __restrict__ x, const float* __restrict__ w,
                                float* __restrict__ y, __half* __restrict__ hi,
                                __half* __restrict__ lo) {
    int row = blockIdx.x;
    const float* xr = x + (size_t)row * CC;
    float* yr = y + (size_t)row * CC;
    float v[4];
    float ss = 0.f;
#pragma unroll
    for (int i = 0; i < 4; i++) {
        v[i] = xr[threadIdx.x + i * 256];
        ss += v[i] * v[i];
    }
#pragma unroll
    for (int off = 16; off; off >>= 1) ss += __shfl_xor_sync(0xffffffffu, ss, off);
    __shared__ float sred[8];
    __shared__ float stot;
    if ((threadIdx.x & 31) == 0) sred[threadIdx.x >> 5] = ss;
    __syncthreads();
    if (threadIdx.x < 8) {
        float t = sred[threadIdx.x];
#pragma unroll
        for (int off = 4; off; off >>= 1) t += __shfl_xor_sync(0xffu, t, off);
        if (threadIdx.x == 0) stot = t;
    }
    __syncthreads();
    float r = rsqrtf(stot / (float)CC + 1e-6f);
#pragma unroll
    for (int i = 0; i < 4; i++)
        yr[threadIdx.x + i * 256] = v[i] * r * w[threadIdx.x + i * 256];
    __syncthreads();
    float4 vv = ((const float4*)yr)[threadIdx.x];
    split_store_h(hi + (size_t)row * CC, lo + (size_t)row * CC, threadIdx.x, vv);
}

// ---------------- beta: fused dot + bias + sigmoid ---------------------------
__global__ __launch_bounds__(512)
void beta_k(const float* __restrict__ xn, const float* __restrict__ bw,
            const float* __restrict__ bias, float* __restrict__ beta) {
    __shared__ float xs[CC];
    const int row = blockIdx.x;
    for (int i = threadIdx.x; i < CC; i += 512) xs[i] = xn[(size_t)row * CC + i];
    __syncthreads();
    const int h = threadIdx.x >> 5;
    const int lane = threadIdx.x & 31;
    const float* w = bw + (size_t)h * CC;
    float acc = 0.f;
#pragma unroll 8
    for (int j = lane; j < CC; j += 32) acc += xs[j] * w[j];
#pragma unroll
    for (int off = 16; off; off >>= 1) acc += __shfl_xor_sync(0xffffffffu, acc, off);
    if (lane == 0) {
        float t = acc + bias[h];
        beta[(size_t)row * HH + h] = 1.f / (1.f + __expf(-t));
    }
}

// ---------------- l2norm over q,k (merged QKVG layout, ld=4096) --------------
__global__ void l2norm_qk_k(float* __restrict__ ff) {
    int vec = blockIdx.x * 8 + (threadIdx.x >> 5);  // 8192 rows * 32 segs
    int lane = threadIdx.x & 31;
    int row = vec >> 5;
    int seg = vec & 31;                              // 0-15 q heads, 16-31 k heads
    float* p = ff + (size_t)row * 4096 + seg * 64;
    float a = p[lane], b = p[lane + 32];
    float ss = a * a + b * b;
#pragma unroll
    for (int off = 16; off; off >>= 1) ss += __shfl_xor_sync(0xffffffffu, ss, off);
    float inv = 1.f / fmaxf(sqrtf(ss), 1e-12f);
    p[lane] = a * inv;
    p[lane + 32] = b * inv;
}

// sigmoid(gate)*o -> split (gate at ff col 3072, ld 4096)
__global__ void gate_mul_split_k(const float* __restrict__ ff, const float* __restrict__ o,
                                 __half* __restrict__ hi, __half* __restrict__ lo) {
    int row = blockIdx.x;
    int t = threadIdx.x;                            // 256 threads, 1 float4 each
    float4 gv = ((const float4*)(ff + (size_t)row * 4096 + 3072))[t];
    float4 ov = ((const float4*)(o + (size_t)row * CC))[t];
    float4 r;
    r.x = ov.x / (1.f + __expf(-gv.x));
    r.y = ov.y / (1.f + __expf(-gv.y));
    r.z = ov.z / (1.f + __expf(-gv.z));
    r.w = ov.w / (1.f + __expf(-gv.w));
    split_store_h(hi + (size_t)row * CC, lo + (size_t)row * CC, t, r);
}

// silu(g)*u -> split (merged FFN layout, ld=8192: g cols 0-4095, u cols 4096-8191)
__global__ void silu_mul_split_k(const float* __restrict__ ff,
                                 __half* __restrict__ hi, __half* __restrict__ lo) {
    int row = blockIdx.x;
    const float4* g4 = (const float4*)(ff + (size_t)row * 2 * FF);
    const float4* u4 = g4 + FF / 4;
    __half* hrow = hi + (size_t)row * FF;
    __half* lrow = lo + (size_t)row * FF;
#pragma unroll
    for (int i = threadIdx.x; i < FF / 4; i += 256) {
        float4 gv = g4[i];
        float4 uv = u4[i];
        float4 r;
        r.x = (gv.x / (1.f + __expf(-gv.x))) * uv.x;
        r.y = (gv.y / (1.f + __expf(-gv.y))) * uv.y;
        r.z = (gv.z / (1.f + __expf(-gv.z))) * uv.z;
        r.w = (gv.w / (1.f + __expf(-gv.w))) * uv.w;
        split_store_h(hrow, lrow, i, r);
    }
}

// ---------------- delta-rule scan (q/k/v in merged layout, ld=4096) ----------
__global__ __launch_bounds__(128)
void delta_scan_k(const float* __restrict__ ff, const float* __restrict__ beta,
                  float* __restrict__ o) {
    const int b = blockIdx.x / HH;
    const int h = blockIdx.x % HH;
    const int tid = threadIdx.x;
    const int d = tid >> 1;
    const int s = tid & 1;
    const int cbase = s * 32;
    const int LD = 4096;

    __shared__ float qs[2][64];
    __shared__ float ks[2][64];

    float Mrow[32];
#pragma unroll
    for (int j = 0; j < 32; j++) Mrow[j] = 0.f;

    const float* qb = ff + (size_t)b * TT * LD + h * DD;          // q cols [0,1024)
    const float* kb = qb + 1024;                                   // k
    const float* vb = qb + 2048;                                   // v
    const float* bb = beta + (size_t)b * TT * HH + h;
    float* ob = o + (size_t)b * TT * CC + h * DD;

    float rqk = (tid < 64) ? qb[tid] : kb[tid - 64];
    float rv = vb[d];
    float rb = bb[0];

    int buf = 0;
    for (int t = 0; t < TT; t++) {
        if (tid < 64) qs[buf][tid] = rqk; else ks[buf][tid - 64] = rqk;
        __syncthreads();
        float cv = rv, cb = rb;
        if (t + 1 < TT) {
            const size_t off = (size_t)(t + 1) * LD;
            rqk = (tid < 64) ? qb[off + tid] : kb[off + tid - 64];
            rv = vb[off + d];
            rb = bb[(t + 1) * HH];
        }
        float po0 = 0.f, po1 = 0.f, pm0 = 0.f, pm1 = 0.f;
#pragma unroll
        for (int j = 0; j < 32; j += 2) {
            float q0 = qs[buf][cbase + j], q1 = qs[buf][cbase + j + 1];
            float k0 = ks[buf][cbase + j], k1 = ks[buf][cbase + j + 1];
            po0 += Mrow[j] * q0;
            po1 += Mrow[j + 1] * q1;
            pm0 += Mrow[j] * k0;
            pm1 += Mrow[j + 1] * k1;
        }
        float po = po0 + po1, pm = pm0 + pm1;
        po += __shfl_xor_sync(0xffffffffu, po, 1);
        pm += __shfl_xor_sync(0xffffffffu, pm, 1);
        float dvb = cb * (cv - pm);
#pragma unroll
        for (int j = 0; j < 32; j++) Mrow[j] += dvb * ks[buf][cbase + j];
        if (s == 0) ob[(size_t)t * CC + d] = po;
        buf ^= 1;
    }
}

// ---------------- launch ------------------------------------------------------
extern "C" void kernel_launch(void* const* d_in, const int* in_sizes, int n_in,
                              void* d_out, int out_size) {
    const float* x       = (const float*)d_in[0];
    const float* norm1_w = (const float*)d_in[3];
    const float* norm2_w = (const float*)d_in[4];
    const float* q_w     = (const float*)d_in[5];
    const float* k_w     = (const float*)d_in[6];
    const float* v_w     = (const float*)d_in[7];
    const float* beta_w  = (const float*)d_in[8];
    const float* beta_b  = (const float*)d_in[9];
    const float* gate_w  = (const float*)d_in[10];
    const float* o_w     = (const float*)d_in[11];
    const float* fg_w    = (const float*)d_in[12];
    const float* fu_w    = (const float*)d_in[13];
    const float* fd_w    = (const float*)d_in[14];
    float* out = (float*)d_out;

    float *xn, *o, *x1, *beta, *ff;
    __half *ah, *al, *wh;
    cudaGetSymbolAddress((void**)&xn,   g_xn);
    cudaGetSymbolAddress((void**)&o,    g_o);
    cudaGetSymbolAddress((void**)&x1,   g_x1);
    cudaGetSymbolAddress((void**)&beta, g_beta);
    cudaGetSymbolAddress((void**)&ff,   g_ff);
    cudaGetSymbolAddress((void**)&ah,   g_a_hi);
    cudaGetSymbolAddress((void**)&al,   g_a_lo);
    cudaGetSymbolAddress((void**)&wh,   g_w_hi);

    cudaFuncSetAttribute(gemm_mma, cudaFuncAttributeMaxDynamicSharedMemorySize,
                         GSMEM_TOTAL);

    auto gemm = [&](float* Cm, const float* R, int N, int K) {
        gemm_mma<<<dim3(N / TILE_N, MROWS / TILE_M), GTHREADS, GSMEM_TOTAL>>>(
            Cm, R, ah, al, wh, MROWS, N, K);
    };

    // ---- attention branch ----
    rmsnorm_split_k<<<MROWS, 256>>>(x, norm1_w, xn, ah, al);
    cvt_qkvg_k<<<4 * (CC * CC / 4) / 256, 256>>>(q_w, k_w, v_w, gate_w, wh);
    gemm(ff, nullptr, 4 * CC, CC);                       // QKVG, out ld=4096
    beta_k<<<MROWS, 512>>>(xn, beta_w, beta_b, beta);
    l2norm_qk_k<<<(MROWS * 32) / 8, 256>>>(ff);          // q+k in one pass
    delta_scan_k<<<BB * HH, 128>>>(ff, beta, o);
    gate_mul_split_k<<<MROWS, 256>>>(ff, o, ah, al);
    cvt_w_k<<<(CC * CC / 4) / 256, 256>>>(o_w, wh, CC * CC / 4);
    gemm(x1, x, CC, CC);                                 // x1 = x + attn_out

    // ---- FFN branch ----
    rmsnorm_split_k<<<MROWS, 256>>>(x1, norm2_w, xn, ah, al);
    cvt_w_k<<<(FF * CC / 4) / 256, 256>>>(fg_w, wh, FF * CC / 4);
    cvt_w_k<<<(FF * CC / 4) / 256, 256>>>(fu_w, wh + (size_t)FF * CC, FF * CC / 4);
    gemm(ff, nullptr, 2 * FF, CC);                       // gate|up, out ld=8192
    silu_mul_split_k<<<MROWS, 256>>>(ff, ah, al);
    cvt_w_k<<<(CC * FF / 4) / 256, 256>>>(fd_w, wh, CC * FF / 4);
    gemm(out, x1, CC, FF);                               // out = x1 + ffn_out
}

// round 13
// speedup vs baseline: 1.8611x; 1.3024x over previous
#include <cuda_runtime.h>
#include <cuda_fp16.h>
#include <cstdint>
#include <math.h>

#define BB 4
#define TT 2048
#define CC 1024
#define HH 16
#define DD 64
#define FF 4096
#define MROWS (BB*TT)   // 8192

// ---------------- scratch (static device globals; no allocation) -------------
__device__ float g_xn[MROWS*CC];
__device__ float g_o[MROWS*CC];
__device__ float g_x1[MROWS*CC];
__device__ float g_beta[MROWS*HH];
__device__ float g_ff[MROWS*2*FF];              // QKVG out (ld 4096) / FFN out (ld 8192)
__device__ __align__(16) __half g_a_hi[MROWS*FF];
__device__ __align__(16) __half g_w_hi[2*FF*CC];

// ================= PTX helpers (sm_80-era, plain-target safe) ================
__device__ __forceinline__ uint32_t smem_u32(const void* p) {
    return (uint32_t)__cvta_generic_to_shared(p);
}
__device__ __forceinline__ void cp16(uint32_t dst, const void* src) {
    asm volatile("cp.async.cg.shared.global [%0], [%1], 16;\n" :: "r"(dst), "l"(src));
}
__device__ __forceinline__ void cp_commit() {
    asm volatile("cp.async.commit_group;\n" ::: "memory");
}
__device__ __forceinline__ void ldsm4(uint32_t* d, uint32_t addr) {
    asm volatile("ldmatrix.sync.aligned.m8n8.x4.shared.b16 {%0,%1,%2,%3}, [%4];"
                 : "=r"(d[0]), "=r"(d[1]), "=r"(d[2]), "=r"(d[3]) : "r"(addr));
}
__device__ __forceinline__ void mma_fp16(float* c, const uint32_t* a,
                                         uint32_t b0, uint32_t b1) {
    asm volatile(
        "mma.sync.aligned.m16n8k16.row.col.f32.f16.f16.f32 "
        "{%0,%1,%2,%3}, {%4,%5,%6,%7}, {%8,%9}, {%0,%1,%2,%3};"
        : "+f"(c[0]), "+f"(c[1]), "+f"(c[2]), "+f"(c[3])
        : "r"(a[0]), "r"(a[1]), "r"(a[2]), "r"(a[3]), "r"(b0), "r"(b1));
}

// ================= fp16 GEMM via mma.sync ====================================
// C[M,N] = Ah[M,K] * Bh[N,K]^T (+ optional residual R), fp32 accumulate.
// Single pass (A and B truncated to fp16): measured error budget shows
// B-trunc alone = 1.19e-4; adding independent A-trunc ~ sqrt(2)x, well under 1e-3.
// CTA 128x256, 512 threads, warp tile 32x64, KT=64.
// 3 smem stages (144KB), prefetch distance 2, single __syncthreads per chunk.
#define TILE_M 128
#define TILE_N 256
#define KT 64
#define OFF_B    (16*1024)           // A: 128 rows x 128B = 16KB, then B 32KB
#define STAGE_BYTES (48*1024)
#define GSMEM_TOTAL (3*STAGE_BYTES)  // 144KB
#define GTHREADS 512

__device__ __forceinline__ void load_tile(const __half* __restrict__ g, int ldk,
                                          int row0, int k0, uint32_t dstbase,
                                          int rows, int tid) {
#pragma unroll
    for (int i = tid; i < rows * 8; i += GTHREADS) {
        int r = i >> 3;
        int c16 = i & 7;
        const __half* src = g + (size_t)(row0 + r) * ldk + k0 + c16 * 8;
        uint32_t dst = dstbase + r * 128 + (((uint32_t)(c16 ^ (r & 7))) << 4);
        cp16(dst, src);
    }
}

__device__ __forceinline__ void load_stage(const __half* Ah, const __half* Bh,
                                           int K, int bm, int bn,
                                           int k0, uint32_t sb, int tid) {
    load_tile(Ah, K, bm, k0, sb, 128, tid);
    load_tile(Bh, K, bn, k0, sb + OFF_B, 256, tid);
    cp_commit();
}

__global__ __launch_bounds__(GTHREADS, 1)
void gemm_mma(float* __restrict__ C, const float* __restrict__ R,
              const __half* __restrict__ Ah, const __half* __restrict__ Bh,
              int M, int N, int K) {
    extern __shared__ __align__(1024) char smem[];
    const uint32_t sbase = smem_u32(smem);
    const int tid = threadIdx.x;
    const int wid = tid >> 5;
    const int lane = tid & 31;
    const int wm = wid & 3;
    const int wn = wid >> 2;
    const int bm = blockIdx.y * TILE_M;
    const int bn = blockIdx.x * TILE_N;

    const int mi = lane >> 3;
    const int lr = lane & 7;
    const uint32_t a_off = (uint32_t)(wm * 32 + ((mi & 1) << 3) + lr) * 128;
    const uint32_t a_cb = (uint32_t)(mi >> 1);
    const uint32_t b_off = (uint32_t)(wn * 64 + ((mi >> 1) << 3) + lr) * 128;
    const uint32_t b_cb = (uint32_t)(mi & 1);

    float acc[2][8][4];
#pragma unroll
    for (int a = 0; a < 2; a++)
#pragma unroll
        for (int b = 0; b < 8; b++)
#pragma unroll
            for (int c = 0; c < 4; c++) acc[a][b][c] = 0.f;

    const int NC = K / KT;

    load_stage(Ah, Bh, K, bm, bn, 0, sbase, tid);
    load_stage(Ah, Bh, K, bm, bn, KT, sbase + STAGE_BYTES, tid);

    for (int kc = 0; kc < NC; kc++) {
        if (kc + 1 < NC) {
            asm volatile("cp.async.wait_group 1;\n" ::: "memory");
        } else {
            asm volatile("cp.async.wait_group 0;\n" ::: "memory");
        }
        __syncthreads();
        if (kc + 2 < NC) {
            load_stage(Ah, Bh, K, bm, bn, (kc + 2) * KT,
                       sbase + (uint32_t)((kc + 2) % 3) * STAGE_BYTES, tid);
        }
        const uint32_t sb = sbase + (uint32_t)(kc % 3) * STAGE_BYTES;

#pragma unroll
        for (int ki = 0; ki < 4; ki++) {
            uint32_t ah[2][4], bh[4][4];
            const uint32_t ax = ((uint32_t)(ki * 2) + a_cb) ^ (uint32_t)lr;
            const uint32_t bx = ((uint32_t)(ki * 2) + b_cb) ^ (uint32_t)lr;
#pragma unroll
            for (int mt = 0; mt < 2; mt++) {
                uint32_t aaddr = sb + a_off + (uint32_t)(mt * 2048) + (ax << 4);
                ldsm4(ah[mt], aaddr);
            }
#pragma unroll
            for (int nt = 0; nt < 4; nt++) {
                uint32_t baddr = sb + OFF_B + b_off + (uint32_t)(nt * 2048) + (bx << 4);
                ldsm4(bh[nt], baddr);
            }
#pragma unroll
            for (int mt = 0; mt < 2; mt++)
#pragma unroll
                for (int nt = 0; nt < 4; nt++)
#pragma unroll
                    for (int h = 0; h < 2; h++)
                        mma_fp16(acc[mt][nt * 2 + h], ah[mt],
                                 bh[nt][2 * h], bh[nt][2 * h + 1]);
        }
    }

    const int g = lane >> 2;
    const int t = lane & 3;
#pragma unroll
    for (int mt = 0; mt < 2; mt++) {
        const int row0 = bm + wm * 32 + mt * 16 + g;
#pragma unroll
        for (int n8 = 0; n8 < 8; n8++) {
            const int col = bn + wn * 64 + n8 * 8 + t * 2;
            float* c = acc[mt][n8];
            if (R) {
                const float* r0 = R + (size_t)row0 * N + col;
                const float* r1 = R + (size_t)(row0 + 8) * N + col;
                *(float2*)(C + (size_t)row0 * N + col) =
                    make_float2(c[0] + r0[0], c[1] + r0[1]);
                *(float2*)(C + (size_t)(row0 + 8) * N + col) =
                    make_float2(c[2] + r1[0], c[3] + r1[1]);
            } else {
                *(float2*)(C + (size_t)row0 * N + col)       = make_float2(c[0], c[1]);
                *(float2*)(C + (size_t)(row0 + 8) * N + col) = make_float2(c[2], c[3]);
            }
        }
    }
}

// ---------------- fp32 -> fp16 stores ----------------------------------------
__device__ __forceinline__ void store_h4(__half* hi, int i4, float4 v) {
    ((__half2*)hi)[2 * i4]     = __halves2half2(__float2half_rn(v.x), __float2half_rn(v.y));
    ((__half2*)hi)[2 * i4 + 1] = __halves2half2(__float2half_rn(v.z), __float2half_rn(v.w));
}

__global__ void cvt_w_k(const float* __restrict__ x, __half* __restrict__ hi, int n4) {
    int i = blockIdx.x * 256 + threadIdx.x;
    if (i >= n4) return;
    store_h4(hi, i, ((const float4*)x)[i]);
}

// merged q/k/v/gate weight convert -> wh rows [0,4C)
__global__ void cvt_qkvg_k(const float* __restrict__ qw, const float* __restrict__ kw,
                           const float* __restrict__ vw, const float* __restrict__ gw,
                           __half* __restrict__ hi) {
    int i = blockIdx.x * 256 + threadIdx.x;
    int region = i >> 18;                          // CC*CC/4 = 262144
    int j = i & 0x3FFFF;
    const float* src = (region == 0) ? qw : (region == 1) ? kw : (region == 2) ? vw : gw;
    store_h4(hi + ((size_t)region << 20), j, ((const float4*)src)[j]);
}

// ---------------- rmsnorm (fp16 output fused) ---------------------------------
__global__ void rmsnorm_h_k(const float* __restrict__ x, const float* __restrict__ w,
                            float* __restrict__ y, __half* __restrict__ hi) {
    int row = blockIdx.x;
    const float* xr = x + (size_t)row * CC;
    float* yr = y + (size_t)row * CC;
    float v[4];
    float ss = 0.f;
#pragma unroll
    for (int i = 0; i < 4; i++) {
        v[i] = xr[threadIdx.x + i * 256];
        ss += v[i] * v[i];
    }
#pragma unroll
    for (int off = 16; off; off >>= 1) ss += __shfl_xor_sync(0xffffffffu, ss, off);
    __shared__ float sred[8];
    __shared__ float stot;
    if ((threadIdx.x & 31) == 0) sred[threadIdx.x >> 5] = ss;
    __syncthreads();
    if (threadIdx.x < 8) {
        float t = sred[threadIdx.x];
#pragma unroll
        for (int off = 4; off; off >>= 1) t += __shfl_xor_sync(0xffu, t, off);
        if (threadIdx.x == 0) stot = t;
    }
    __syncthreads();
    float r = rsqrtf(stot / (float)CC + 1e-6f);
#pragma unroll
    for (int i = 0; i < 4; i++)
        yr[threadIdx.x + i * 256] = v[i] * r * w[threadIdx.x + i * 256];
    __syncthreads();
    float4 vv = ((const float4*)yr)[threadIdx.x];
    store_h4(hi + (size_t)row * CC, threadIdx.x, vv);
}

// ---------------- beta: fused dot + bias + sigmoid ---------------------------
__global__ __launch_bounds__(512)
void beta_k(const float* __restrict__ xn, const float* __restrict__ bw,
            const float* __restrict__ bias, float* __restrict__ beta) {
    __shared__ float xs[CC];
    const int row = blockIdx.x;
    for (int i = threadIdx.x; i < CC; i += 512) xs[i] = xn[(size_t)row * CC + i];
    __syncthreads();
    const int h = threadIdx.x >> 5;
    const int lane = threadIdx.x & 31;
    const float* w = bw + (size_t)h * CC;
    float acc = 0.f;
#pragma unroll 8
    for (int j = lane; j < CC; j += 32) acc += xs[j] * w[j];
#pragma unroll
    for (int off = 16; off; off >>= 1) acc += __shfl_xor_sync(0xffffffffu, acc, off);
    if (lane == 0) {
        float t = acc + bias[h];
        beta[(size_t)row * HH + h] = 1.f / (1.f + __expf(-t));
    }
}

// ---------------- l2norm over q,k (merged QKVG layout, ld=4096) --------------
__global__ void l2norm_qk_k(float* __restrict__ ff) {
    int vec = blockIdx.x * 8 + (threadIdx.x >> 5);
    int lane = threadIdx.x & 31;
    int row = vec >> 5;
    int seg = vec & 31;
    float* p = ff + (size_t)row * 4096 + seg * 64;
    float a = p[lane], b = p[lane + 32];
    float ss = a * a + b * b;
#pragma unroll
    for (int off = 16; off; off >>= 1) ss += __shfl_xor_sync(0xffffffffu, ss, off);
    float inv = 1.f / fmaxf(sqrtf(ss), 1e-12f);
    p[lane] = a * inv;
    p[lane + 32] = b * inv;
}

// sigmoid(gate)*o -> fp16 (gate at ff col 3072, ld 4096)
__global__ void gate_mul_h_k(const float* __restrict__ ff, const float* __restrict__ o,
                             __half* __restrict__ hi) {
    int row = blockIdx.x;
    int t = threadIdx.x;
    float4 gv = ((const float4*)(ff + (size_t)row * 4096 + 3072))[t];
    float4 ov = ((const float4*)(o + (size_t)row * CC))[t];
    float4 r;
    r.x = ov.x / (1.f + __expf(-gv.x));
    r.y = ov.y / (1.f + __expf(-gv.y));
    r.z = ov.z / (1.f + __expf(-gv.z));
    r.w = ov.w / (1.f + __expf(-gv.w));
    store_h4(hi + (size_t)row * CC, t, r);
}

// silu(g)*u -> fp16 (merged FFN layout, ld=8192)
__global__ void silu_mul_h_k(const float* __restrict__ ff, __half* __restrict__ hi) {
    int row = blockIdx.x;
    const float4* g4 = (const float4*)(ff + (size_t)row * 2 * FF);
    const float4* u4 = g4 + FF / 4;
    __half* hrow = hi + (size_t)row * FF;
#pragma unroll
    for (int i = threadIdx.x; i < FF / 4; i += 256) {
        float4 gv = g4[i];
        float4 uv = u4[i];
        float4 r;
        r.x = (gv.x / (1.f + __expf(-gv.x))) * uv.x;
        r.y = (gv.y / (1.f + __expf(-gv.y))) * uv.y;
        r.z = (gv.z / (1.f + __expf(-gv.z))) * uv.z;
        r.w = (gv.w / (1.f + __expf(-gv.w))) * uv.w;
        store_h4(hrow, i, r);
    }
}

// ---------------- delta-rule scan (q/k/v in merged layout, ld=4096) ----------
__global__ __launch_bounds__(128)
void delta_scan_k(const float* __restrict__ ff, const float* __restrict__ beta,
                  float* __restrict__ o) {
    const int b = blockIdx.x / HH;
    const int h = blockIdx.x % HH;
    const int tid = threadIdx.x;
    const int d = tid >> 1;
    const int s = tid & 1;
    const int cbase = s * 32;
    const int LD = 4096;

    __shared__ float qs[2][64];
    __shared__ float ks[2][64];

    float Mrow[32];
#pragma unroll
    for (int j = 0; j < 32; j++) Mrow[j] = 0.f;

    const float* qb = ff + (size_t)b * TT * LD + h * DD;
    const float* kb = qb + 1024;
    const float* vb = qb + 2048;
    const float* bb = beta + (size_t)b * TT * HH + h;
    float* ob = o + (size_t)b * TT * CC + h * DD;

    float rqk = (tid < 64) ? qb[tid] : kb[tid - 64];
    float rv = vb[d];
    float rb = bb[0];

    int buf = 0;
    for (int t = 0; t < TT; t++) {
        if (tid < 64) qs[buf][tid] = rqk; else ks[buf][tid - 64] = rqk;
        __syncthreads();
        float cv = rv, cb = rb;
        if (t + 1 < TT) {
            const size_t off = (size_t)(t + 1) * LD;
            rqk = (tid < 64) ? qb[off + tid] : kb[off + tid - 64];
            rv = vb[off + d];
            rb = bb[(t + 1) * HH];
        }
        float po0 = 0.f, po1 = 0.f, pm0 = 0.f, pm1 = 0.f;
#pragma unroll
        for (int j = 0; j < 32; j += 2) {
            float q0 = qs[buf][cbase + j], q1 = qs[buf][cbase + j + 1];
            float k0 = ks[buf][cbase + j], k1 = ks[buf][cbase + j + 1];
            po0 += Mrow[j] * q0;
            po1 += Mrow[j + 1] * q1;
            pm0 += Mrow[j] * k0;
            pm1 += Mrow[j + 1] * k1;
        }
        float po = po0 + po1, pm = pm0 + pm1;
        po += __shfl_xor_sync(0xffffffffu, po, 1);
        pm += __shfl_xor_sync(0xffffffffu, pm, 1);
        float dvb = cb * (cv - pm);
#pragma unroll
        for (int j = 0; j < 32; j++) Mrow[j] += dvb * ks[buf][cbase + j];
        if (s == 0) ob[(size_t)t * CC + d] = po;
        buf ^= 1;
    }
}

// ---------------- launch ------------------------------------------------------
extern "C" void kernel_launch(void* const* d_in, const int* in_sizes, int n_in,
                              void* d_out, int out_size) {
    const float* x       = (const float*)d_in[0];
    const float* norm1_w = (const float*)d_in[3];
    const float* norm2_w = (const float*)d_in[4];
    const float* q_w     = (const float*)d_in[5];
    const float* k_w     = (const float*)d_in[6];
    const float* v_w     = (const float*)d_in[7];
    const float* beta_w  = (const float*)d_in[8];
    const float* beta_b  = (const float*)d_in[9];
    const float* gate_w  = (const float*)d_in[10];
    const float* o_w     = (const float*)d_in[11];
    const float* fg_w    = (const float*)d_in[12];
    const float* fu_w    = (const float*)d_in[13];
    const float* fd_w    = (const float*)d_in[14];
    float* out = (float*)d_out;

    float *xn, *o, *x1, *beta, *ff;
    __half *ah, *wh;
    cudaGetSymbolAddress((void**)&xn,   g_xn);
    cudaGetSymbolAddress((void**)&o,    g_o);
    cudaGetSymbolAddress((void**)&x1,   g_x1);
    cudaGetSymbolAddress((void**)&beta, g_beta);
    cudaGetSymbolAddress((void**)&ff,   g_ff);
    cudaGetSymbolAddress((void**)&ah,   g_a_hi);
    cudaGetSymbolAddress((void**)&wh,   g_w_hi);

    cudaFuncSetAttribute(gemm_mma, cudaFuncAttributeMaxDynamicSharedMemorySize,
                         GSMEM_TOTAL);

    auto gemm = [&](float* Cm, const float* R, int N, int K) {
        gemm_mma<<<dim3(N / TILE_N, MROWS / TILE_M), GTHREADS, GSMEM_TOTAL>>>(
            Cm, R, ah, wh, MROWS, N, K);
    };

    // ---- attention branch ----
    rmsnorm_h_k<<<MROWS, 256>>>(x, norm1_w, xn, ah);
    cvt_qkvg_k<<<4 * (CC * CC / 4) / 256, 256>>>(q_w, k_w, v_w, gate_w, wh);
    gemm(ff, nullptr, 4 * CC, CC);                       // QKVG, out ld=4096
    beta_k<<<MROWS, 512>>>(xn, beta_w, beta_b, beta);
    l2norm_qk_k<<<(MROWS * 32) / 8, 256>>>(ff);
    delta_scan_k<<<BB * HH, 128>>>(ff, beta, o);
    gate_mul_h_k<<<MROWS, 256>>>(ff, o, ah);
    cvt_w_k<<<(CC * CC / 4) / 256, 256>>>(o_w, wh, CC * CC / 4);
    gemm(x1, x, CC, CC);                                 // x1 = x + attn_out

    // ---- FFN branch ----
    rmsnorm_h_k<<<MROWS, 256>>>(x1, norm2_w, xn, ah);
    cvt_w_k<<<(FF * CC / 4) / 256, 256>>>(fg_w, wh, FF * CC / 4);
    cvt_w_k<<<(FF * CC / 4) / 256, 256>>>(fu_w, wh + (size_t)FF * CC, FF * CC / 4);
    gemm(ff, nullptr, 2 * FF, CC);                       // gate|up, out ld=8192
    silu_mul_h_k<<<MROWS, 256>>>(ff, ah);
    cvt_w_k<<<(CC * FF / 4) / 256, 256>>>(fd_w, wh, CC * FF / 4);
    gemm(out, x1, CC, FF);                               // out = x1 + ffn_out
}

// round 15
// speedup vs baseline: 1.8625x; 1.0007x over previous
#include <cuda_runtime.h>
#include <cuda_fp16.h>
#include <cstdint>
#include <math.h>

#define BB 4
#define TT 2048
#define CC 1024
#define HH 16
#define DD 64
#define FF 4096
#define MROWS (BB*TT)   // 8192

// ---------------- scratch (static device globals; no allocation) -------------
__device__ float g_xn[MROWS*CC];
__device__ float g_o[MROWS*CC];
__device__ float g_x1[MROWS*CC];
__device__ float g_beta[MROWS*HH];
__device__ float g_ff[MROWS*4*CC];              // QKVG out (ld 4096)
__device__ __align__(16) __half g_a_hi[MROWS*CC];   // fp16 activations (ld CC)
__device__ __align__(16) __half g_swi[MROWS*FF];    // fused SwiGLU out (ld FF)
__device__ __align__(16) __half g_w_hi[2*FF*CC];

// ================= PTX helpers (sm_80-era, plain-target safe) ================
__device__ __forceinline__ uint32_t smem_u32(const void* p) {
    return (uint32_t)__cvta_generic_to_shared(p);
}
__device__ __forceinline__ void cp16(uint32_t dst, const void* src) {
    asm volatile("cp.async.cg.shared.global [%0], [%1], 16;\n" :: "r"(dst), "l"(src));
}
__device__ __forceinline__ void cp_commit() {
    asm volatile("cp.async.commit_group;\n" ::: "memory");
}
__device__ __forceinline__ void ldsm4(uint32_t* d, uint32_t addr) {
    asm volatile("ldmatrix.sync.aligned.m8n8.x4.shared.b16 {%0,%1,%2,%3}, [%4];"
                 : "=r"(d[0]), "=r"(d[1]), "=r"(d[2]), "=r"(d[3]) : "r"(addr));
}
__device__ __forceinline__ void mma_fp16(float* c, const uint32_t* a,
                                         uint32_t b0, uint32_t b1) {
    asm volatile(
        "mma.sync.aligned.m16n8k16.row.col.f32.f16.f16.f32 "
        "{%0,%1,%2,%3}, {%4,%5,%6,%7}, {%8,%9}, {%0,%1,%2,%3};"
        : "+f"(c[0]), "+f"(c[1]), "+f"(c[2]), "+f"(c[3])
        : "r"(a[0]), "r"(a[1]), "r"(a[2]), "r"(a[3]), "r"(b0), "r"(b1));
}

// ================= fp16 GEMM via mma.sync ====================================
// C[M,N] = Ah[M,K] * Bh[N,K]^T, fp32 accumulate.
// mode 0: fp32 out to C (+ optional residual R)
// mode 1: SwiGLU-fused: B rows interleaved (even=gate, odd=up); writes
//         silu(g)*u as fp16 to Hout (row stride N/2). Hout MUST NOT alias Ah
//         (R14 failed on exactly that: in-place write raced cross-CTA A reads).
// CTA 128x256, 512 threads, warp tile 32x64, KT=64.
// 3 smem stages (144KB), prefetch distance 2, single __syncthreads per chunk.
#define TILE_M 128
#define TILE_N 256
#define KT 64
#define OFF_B    (16*1024)
#define STAGE_BYTES (48*1024)
#define GSMEM_TOTAL (3*STAGE_BYTES)  // 144KB
#define GTHREADS 512

__device__ __forceinline__ void load_tile(const __half* __restrict__ g, int ldk,
                                          int row0, int k0, uint32_t dstbase,
                                          int rows, int tid) {
#pragma unroll
    for (int i = tid; i < rows * 8; i += GTHREADS) {
        int r = i >> 3;
        int c16 = i & 7;
        const __half* src = g + (size_t)(row0 + r) * ldk + k0 + c16 * 8;
        uint32_t dst = dstbase + r * 128 + (((uint32_t)(c16 ^ (r & 7))) << 4);
        cp16(dst, src);
    }
}

__device__ __forceinline__ void load_stage(const __half* Ah, const __half* Bh,
                                           int K, int bm, int bn,
                                           int k0, uint32_t sb, int tid) {
    load_tile(Ah, K, bm, k0, sb, 128, tid);
    load_tile(Bh, K, bn, k0, sb + OFF_B, 256, tid);
    cp_commit();
}

__global__ __launch_bounds__(GTHREADS, 1)
void gemm_mma(float* __restrict__ C, const float* __restrict__ R,
              __half* __restrict__ Hout,
              const __half* __restrict__ Ah, const __half* __restrict__ Bh,
              int M, int N, int K, int mode) {
    extern __shared__ __align__(1024) char smem[];
    const uint32_t sbase = smem_u32(smem);
    const int tid = threadIdx.x;
    const int wid = tid >> 5;
    const int lane = tid & 31;
    const int wm = wid & 3;
    const int wn = wid >> 2;
    const int bm = blockIdx.y * TILE_M;
    const int bn = blockIdx.x * TILE_N;

    const int mi = lane >> 3;
    const int lr = lane & 7;
    const uint32_t a_off = (uint32_t)(wm * 32 + ((mi & 1) << 3) + lr) * 128;
    const uint32_t a_cb = (uint32_t)(mi >> 1);
    const uint32_t b_off = (uint32_t)(wn * 64 + ((mi >> 1) << 3) + lr) * 128;
    const uint32_t b_cb = (uint32_t)(mi & 1);

    float acc[2][8][4];
#pragma unroll
    for (int a = 0; a < 2; a++)
#pragma unroll
        for (int b = 0; b < 8; b++)
#pragma unroll
            for (int c = 0; c < 4; c++) acc[a][b][c] = 0.f;

    const int NC = K / KT;

    load_stage(Ah, Bh, K, bm, bn, 0, sbase, tid);
    load_stage(Ah, Bh, K, bm, bn, KT, sbase + STAGE_BYTES, tid);

    for (int kc = 0; kc < NC; kc++) {
        if (kc + 1 < NC) {
            asm volatile("cp.async.wait_group 1;\n" ::: "memory");
        } else {
            asm volatile("cp.async.wait_group 0;\n" ::: "memory");
        }
        __syncthreads();
        if (kc + 2 < NC) {
            load_stage(Ah, Bh, K, bm, bn, (kc + 2) * KT,
                       sbase + (uint32_t)((kc + 2) % 3) * STAGE_BYTES, tid);
        }
        const uint32_t sb = sbase + (uint32_t)(kc % 3) * STAGE_BYTES;

#pragma unroll
        for (int ki = 0; ki < 4; ki++) {
            uint32_t ah[2][4], bh[4][4];
            const uint32_t ax = ((uint32_t)(ki * 2) + a_cb) ^ (uint32_t)lr;
            const uint32_t bx = ((uint32_t)(ki * 2) + b_cb) ^ (uint32_t)lr;
#pragma unroll
            for (int mt = 0; mt < 2; mt++) {
                uint32_t aaddr = sb + a_off + (uint32_t)(mt * 2048) + (ax << 4);
                ldsm4(ah[mt], aaddr);
            }
#pragma unroll
            for (int nt = 0; nt < 4; nt++) {
                uint32_t baddr = sb + OFF_B + b_off + (uint32_t)(nt * 2048) + (bx << 4);
                ldsm4(bh[nt], baddr);
            }
#pragma unroll
            for (int mt = 0; mt < 2; mt++)
#pragma unroll
                for (int nt = 0; nt < 4; nt++)
#pragma unroll
                    for (int h = 0; h < 2; h++)
                        mma_fp16(acc[mt][nt * 2 + h], ah[mt],
                                 bh[nt][2 * h], bh[nt][2 * h + 1]);
        }
    }

    const int g = lane >> 2;
    const int t = lane & 3;
    if (mode == 1) {
        const int NH = N >> 1;
#pragma unroll
        for (int mt = 0; mt < 2; mt++) {
            const int row0 = bm + wm * 32 + mt * 16 + g;
#pragma unroll
            for (int n8 = 0; n8 < 8; n8++) {
                const int colh = ((bn + wn * 64 + n8 * 8) >> 1) + t;
                float* c = acc[mt][n8];
                float s0 = (c[0] / (1.f + __expf(-c[0]))) * c[1];
                float s1 = (c[2] / (1.f + __expf(-c[2]))) * c[3];
                Hout[(size_t)row0 * NH + colh]       = __float2half_rn(s0);
                Hout[(size_t)(row0 + 8) * NH + colh] = __float2half_rn(s1);
            }
        }
    } else {
#pragma unroll
        for (int mt = 0; mt < 2; mt++) {
            const int row0 = bm + wm * 32 + mt * 16 + g;
#pragma unroll
            for (int n8 = 0; n8 < 8; n8++) {
                const int col = bn + wn * 64 + n8 * 8 + t * 2;
                float* c = acc[mt][n8];
                if (R) {
                    const float* r0 = R + (size_t)row0 * N + col;
                    const float* r1 = R + (size_t)(row0 + 8) * N + col;
                    *(float2*)(C + (size_t)row0 * N + col) =
                        make_float2(c[0] + r0[0], c[1] + r0[1]);
                    *(float2*)(C + (size_t)(row0 + 8) * N + col) =
                        make_float2(c[2] + r1[0], c[3] + r1[1]);
                } else {
                    *(float2*)(C + (size_t)row0 * N + col)       = make_float2(c[0], c[1]);
                    *(float2*)(C + (size_t)(row0 + 8) * N + col) = make_float2(c[2], c[3]);
                }
            }
        }
    }
}

// ---------------- fp32 -> fp16 stores ----------------------------------------
__device__ __forceinline__ void store_h4(__half* hi, int i4, float4 v) {
    ((__half2*)hi)[2 * i4]     = __halves2half2(__float2half_rn(v.x), __float2half_rn(v.y));
    ((__half2*)hi)[2 * i4 + 1] = __halves2half2(__float2half_rn(v.z), __float2half_rn(v.w));
}

__global__ void cvt_w_k(const float* __restrict__ x, __half* __restrict__ hi, int n4) {
    int i = blockIdx.x * 256 + threadIdx.x;
    if (i >= n4) return;
    store_h4(hi, i, ((const float4*)x)[i]);
}

// merged q/k/v/gate weight convert -> wh rows [0,4C)
__global__ void cvt_qkvg_k(const float* __restrict__ qw, const float* __restrict__ kw,
                           const float* __restrict__ vw, const float* __restrict__ gw,
                           __half* __restrict__ hi) {
    int i = blockIdx.x * 256 + threadIdx.x;
    int region = i >> 18;                          // CC*CC/4 = 262144
    int j = i & 0x3FFFF;
    const float* src = (region == 0) ? qw : (region == 1) ? kw : (region == 2) ? vw : gw;
    store_h4(hi + ((size_t)region << 20), j, ((const float4*)src)[j]);
}

// interleaved gate/up convert: wh row 2j = fg row j, row 2j+1 = fu row j
#define ROW4 (CC/4)
__global__ void cvt_gu_k(const float* __restrict__ fg, const float* __restrict__ fu,
                         __half* __restrict__ hi) {
    int i = blockIdx.x * 256 + threadIdx.x;        // over FF*CC/4 float4 positions
    int row = i / ROW4;
    int pos = i % ROW4;
    store_h4(hi, (2 * row) * ROW4 + pos, ((const float4*)fg)[i]);
    store_h4(hi, (2 * row + 1) * ROW4 + pos, ((const float4*)fu)[i]);
}

// ---------------- rmsnorm (fp16 output fused) ---------------------------------
__global__ void rmsnorm_h_k(const float* __restrict__ x, const float* __restrict__ w,
                            float* __restrict__ y, __half* __restrict__ hi) {
    int row = blockIdx.x;
    const float* xr = x + (size_t)row * CC;
    float* yr = y + (size_t)row * CC;
    float v[4];
    float ss = 0.f;
#pragma unroll
    for (int i = 0; i < 4; i++) {
        v[i] = xr[threadIdx.x + i * 256];
        ss += v[i] * v[i];
    }
#pragma unroll
    for (int off = 16; off; off >>= 1) ss += __shfl_xor_sync(0xffffffffu, ss, off);
    __shared__ float sred[8];
    __shared__ float stot;
    if ((threadIdx.x & 31) == 0) sred[threadIdx.x >> 5] = ss;
    __syncthreads();
    if (threadIdx.x < 8) {
        float t = sred[threadIdx.x];
#pragma unroll
        for (int off = 4; off; off >>= 1) t += __shfl_xor_sync(0xffu, t, off);
        if (threadIdx.x == 0) stot = t;
    }
    __syncthreads();
    float r = rsqrtf(stot / (float)CC + 1e-6f);
#pragma unroll
    for (int i = 0; i < 4; i++)
        yr[threadIdx.x + i * 256] = v[i] * r * w[threadIdx.x + i * 256];
    __syncthreads();
    float4 vv = ((const float4*)yr)[threadIdx.x];
    store_h4(hi + (size_t)row * CC, threadIdx.x, vv);
}

// ---------------- beta: persistent, weights cached in shared ------------------
__global__ __launch_bounds__(512)
void beta_k(const float* __restrict__ xn, const float* __restrict__ bw,
            const float* __restrict__ bias, float* __restrict__ beta) {
    extern __shared__ float ws[];                  // 16*1024 floats = 64KB
    for (int i = threadIdx.x; i < HH * CC; i += 512) ws[i] = bw[i];
    __syncthreads();
    const int h = threadIdx.x >> 5;
    const int lane = threadIdx.x & 31;
    const float* w = ws + h * CC;
    const float bi = bias[h];
    for (int row = blockIdx.x; row < MROWS; row += gridDim.x) {
        const float* xr = xn + (size_t)row * CC;
        float acc = 0.f;
#pragma unroll 8
        for (int j = lane; j < CC; j += 32) acc += xr[j] * w[j];
#pragma unroll
        for (int off = 16; off; off >>= 1) acc += __shfl_xor_sync(0xffffffffu, acc, off);
        if (lane == 0)
            beta[(size_t)row * HH + h] = 1.f / (1.f + __expf(-(acc + bi)));
    }
}

// ---------------- l2norm over q,k (merged QKVG layout, ld=4096) --------------
__global__ void l2norm_qk_k(float* __restrict__ ff) {
    int vec = blockIdx.x * 8 + (threadIdx.x >> 5);
    int lane = threadIdx.x & 31;
    int row = vec >> 5;
    int seg = vec & 31;
    float* p = ff + (size_t)row * 4096 + seg * 64;
    float a = p[lane], b = p[lane + 32];
    float ss = a * a + b * b;
#pragma unroll
    for (int off = 16; off; off >>= 1) ss += __shfl_xor_sync(0xffffffffu, ss, off);
    float inv = 1.f / fmaxf(sqrtf(ss), 1e-12f);
    p[lane] = a * inv;
    p[lane + 32] = b * inv;
}

// sigmoid(gate)*o -> fp16 (gate at ff col 3072, ld 4096)
__global__ void gate_mul_h_k(const float* __restrict__ ff, const float* __restrict__ o,
                             __half* __restrict__ hi) {
    int row = blockIdx.x;
    int t = threadIdx.x;
    float4 gv = ((const float4*)(ff + (size_t)row * 4096 + 3072))[t];
    float4 ov = ((const float4*)(o + (size_t)row * CC))[t];
    float4 r;
    r.x = ov.x / (1.f + __expf(-gv.x));
    r.y = ov.y / (1.f + __expf(-gv.y));
    r.z = ov.z / (1.f + __expf(-gv.z));
    r.w = ov.w / (1.f + __expf(-gv.w));
    store_h4(hi + (size_t)row * CC, t, r);
}

// ---------------- delta-rule scan (q/k/v in merged layout, ld=4096) ----------
__global__ __launch_bounds__(128)
void delta_scan_k(const float* __restrict__ ff, const float* __restrict__ beta,
                  float* __restrict__ o) {
    const int b = blockIdx.x / HH;
    const int h = blockIdx.x % HH;
    const int tid = threadIdx.x;
    const int d = tid >> 1;
    const int s = tid & 1;
    const int cbase = s * 32;
    const int LD = 4096;

    __shared__ float qs[2][64];
    __shared__ float ks[2][64];

    float Mrow[32];
#pragma unroll
    for (int j = 0; j < 32; j++) Mrow[j] = 0.f;

    const float* qb = ff + (size_t)b * TT * LD + h * DD;
    const float* kb = qb + 1024;
    const float* vb = qb + 2048;
    const float* bb = beta + (size_t)b * TT * HH + h;
    float* ob = o + (size_t)b * TT * CC + h * DD;

    float rqk = (tid < 64) ? qb[tid] : kb[tid - 64];
    float rv = vb[d];
    float rb = bb[0];

    int buf = 0;
    for (int t = 0; t < TT; t++) {
        if (tid < 64) qs[buf][tid] = rqk; else ks[buf][tid - 64] = rqk;
        __syncthreads();
        float cv = rv, cb = rb;
        if (t + 1 < TT) {
            const size_t off = (size_t)(t + 1) * LD;
            rqk = (tid < 64) ? qb[off + tid] : kb[off + tid - 64];
            rv = vb[off + d];
            rb = bb[(t + 1) * HH];
        }
        float po0 = 0.f, po1 = 0.f, pm0 = 0.f, pm1 = 0.f;
#pragma unroll
        for (int j = 0; j < 32; j += 2) {
            float q0 = qs[buf][cbase + j], q1 = qs[buf][cbase + j + 1];
            float k0 = ks[buf][cbase + j], k1 = ks[buf][cbase + j + 1];
            po0 += Mrow[j] * q0;
            po1 += Mrow[j + 1] * q1;
            pm0 += Mrow[j] * k0;
            pm1 += Mrow[j + 1] * k1;
        }
        float po = po0 + po1, pm = pm0 + pm1;
        po += __shfl_xor_sync(0xffffffffu, po, 1);
        pm += __shfl_xor_sync(0xffffffffu, pm, 1);
        float dvb = cb * (cv - pm);
#pragma unroll
        for (int j = 0; j < 32; j++) Mrow[j] += dvb * ks[buf][cbase + j];
        if (s == 0) ob[(size_t)t * CC + d] = po;
        buf ^= 1;
    }
}

// ---------------- launch ------------------------------------------------------
extern "C" void kernel_launch(void* const* d_in, const int* in_sizes, int n_in,
                              void* d_out, int out_size) {
    const float* x       = (const float*)d_in[0];
    const float* norm1_w = (const float*)d_in[3];
    const float* norm2_w = (const float*)d_in[4];
    const float* q_w     = (const float*)d_in[5];
    const float* k_w     = (const float*)d_in[6];
    const float* v_w     = (const float*)d_in[7];
    const float* beta_w  = (const float*)d_in[8];
    const float* beta_b  = (const float*)d_in[9];
    const float* gate_w  = (const float*)d_in[10];
    const float* o_w     = (const float*)d_in[11];
    const float* fg_w    = (const float*)d_in[12];
    const float* fu_w    = (const float*)d_in[13];
    const float* fd_w    = (const float*)d_in[14];
    float* out = (float*)d_out;

    float *xn, *o, *x1, *beta, *ff;
    __half *ah, *swi, *wh;
    cudaGetSymbolAddress((void**)&xn,   g_xn);
    cudaGetSymbolAddress((void**)&o,    g_o);
    cudaGetSymbolAddress((void**)&x1,   g_x1);
    cudaGetSymbolAddress((void**)&beta, g_beta);
    cudaGetSymbolAddress((void**)&ff,   g_ff);
    cudaGetSymbolAddress((void**)&ah,   g_a_hi);
    cudaGetSymbolAddress((void**)&swi,  g_swi);
    cudaGetSymbolAddress((void**)&wh,   g_w_hi);

    cudaFuncSetAttribute(gemm_mma, cudaFuncAttributeMaxDynamicSharedMemorySize,
                         GSMEM_TOTAL);
    cudaFuncSetAttribute(beta_k, cudaFuncAttributeMaxDynamicSharedMemorySize,
                         HH * CC * (int)sizeof(float));

    auto gemm = [&](float* Cm, const float* R, __half* H, const __half* A,
                    int N, int K, int mode) {
        gemm_mma<<<dim3(N / TILE_N, MROWS / TILE_M), GTHREADS, GSMEM_TOTAL>>>(
            Cm, R, H, A, wh, MROWS, N, K, mode);
    };

    // ---- attention branch ----
    rmsnorm_h_k<<<MROWS, 256>>>(x, norm1_w, xn, ah);
    cvt_qkvg_k<<<4 * (CC * CC / 4) / 256, 256>>>(q_w, k_w, v_w, gate_w, wh);
    gemm(ff, nullptr, nullptr, ah, 4 * CC, CC, 0);       // QKVG, out ld=4096
    beta_k<<<256, 512, HH * CC * sizeof(float)>>>(xn, beta_w, beta_b, beta);
    l2norm_qk_k<<<(MROWS * 32) / 8, 256>>>(ff);
    delta_scan_k<<<BB * HH, 128>>>(ff, beta, o);
    gate_mul_h_k<<<MROWS, 256>>>(ff, o, ah);
    cvt_w_k<<<(CC * CC / 4) / 256, 256>>>(o_w, wh, CC * CC / 4);
    gemm(x1, x, nullptr, ah, CC, CC, 0);                 // x1 = x + attn_out

    // ---- FFN branch ----
    rmsnorm_h_k<<<MROWS, 256>>>(x1, norm2_w, xn, ah);
    cvt_gu_k<<<(FF * CC / 4) / 256, 256>>>(fg_w, fu_w, wh);
    gemm(nullptr, nullptr, swi, ah, 2 * FF, CC, 1);      // fused SwiGLU -> swi (NOT ah)
    cvt_w_k<<<(CC * FF / 4) / 256, 256>>>(fd_w, wh, CC * FF / 4);
    gemm(out, x1, nullptr, swi, CC, FF, 0);              // out = x1 + ffn_out
}

// round 16
// speedup vs baseline: 1.8998x; 1.0200x over previous
#include <cuda_runtime.h>
#include <cuda_fp16.h>
#include <cstdint>
#include <math.h>

#define BB 4
#define TT 2048
#define CC 1024
#define HH 16
#define DD 64
#define FF 4096
#define MROWS (BB*TT)   // 8192

// ---------------- scratch (static device globals; no allocation) -------------
__device__ float g_xn[MROWS*CC];
__device__ float g_o[MROWS*CC];
__device__ float g_x1[MROWS*CC];
__device__ float g_beta[MROWS*HH];
__device__ float g_ff[MROWS*4*CC];                  // QKVG out (ld 4096)
__device__ __align__(16) __half g_a_hi[MROWS*CC];   // fp16 activations (ld CC)
__device__ __align__(16) __half g_swi[MROWS*FF];    // fused SwiGLU out (ld FF)
__device__ __align__(16) __half g_w_qkvg[4*CC*CC];
__device__ __align__(16) __half g_w_o[CC*CC];
__device__ __align__(16) __half g_w_gu[2*FF*CC];
__device__ __align__(16) __half g_w_d[FF*CC];

// ================= PTX helpers (sm_80-era, plain-target safe) ================
__device__ __forceinline__ uint32_t smem_u32(const void* p) {
    return (uint32_t)__cvta_generic_to_shared(p);
}
__device__ __forceinline__ void cp16(uint32_t dst, const void* src) {
    asm volatile("cp.async.cg.shared.global [%0], [%1], 16;\n" :: "r"(dst), "l"(src));
}
__device__ __forceinline__ void cp_commit() {
    asm volatile("cp.async.commit_group;\n" ::: "memory");
}
__device__ __forceinline__ void ldsm4(uint32_t* d, uint32_t addr) {
    asm volatile("ldmatrix.sync.aligned.m8n8.x4.shared.b16 {%0,%1,%2,%3}, [%4];"
                 : "=r"(d[0]), "=r"(d[1]), "=r"(d[2]), "=r"(d[3]) : "r"(addr));
}
__device__ __forceinline__ void mma_fp16(float* c, const uint32_t* a,
                                         uint32_t b0, uint32_t b1) {
    asm volatile(
        "mma.sync.aligned.m16n8k16.row.col.f32.f16.f16.f32 "
        "{%0,%1,%2,%3}, {%4,%5,%6,%7}, {%8,%9}, {%0,%1,%2,%3};"
        : "+f"(c[0]), "+f"(c[1]), "+f"(c[2]), "+f"(c[3])
        : "r"(a[0]), "r"(a[1]), "r"(a[2]), "r"(a[3]), "r"(b0), "r"(b1));
}

// ================= fp16 GEMM via mma.sync ====================================
// C[M,N] = Ah[M,K] * Bh[N,K]^T, fp32 accumulate.
// mode 0: fp32 out to C (+ optional residual R)
// mode 1: SwiGLU-fused (B rows interleaved even=gate odd=up): silu(g)*u fp16
//         to Hout (row stride N/2), staged through smem for coalesced stores.
//         Hout must not alias Ah.
#define TILE_M 128
#define TILE_N 256
#define KT 64
#define OFF_B    (16*1024)
#define STAGE_BYTES (48*1024)
#define GSMEM_TOTAL (3*STAGE_BYTES)  // 144KB
#define GTHREADS 512

__device__ __forceinline__ void load_tile(const __half* __restrict__ g, int ldk,
                                          int row0, int k0, uint32_t dstbase,
                                          int rows, int tid) {
#pragma unroll
    for (int i = tid; i < rows * 8; i += GTHREADS) {
        int r = i >> 3;
        int c16 = i & 7;
        const __half* src = g + (size_t)(row0 + r) * ldk + k0 + c16 * 8;
        uint32_t dst = dstbase + r * 128 + (((uint32_t)(c16 ^ (r & 7))) << 4);
        cp16(dst, src);
    }
}

__device__ __forceinline__ void load_stage(const __half* Ah, const __half* Bh,
                                           int K, int bm, int bn,
                                           int k0, uint32_t sb, int tid) {
    load_tile(Ah, K, bm, k0, sb, 128, tid);
    load_tile(Bh, K, bn, k0, sb + OFF_B, 256, tid);
    cp_commit();
}

__global__ __launch_bounds__(GTHREADS, 1)
void gemm_mma(float* __restrict__ C, const float* __restrict__ R,
              __half* __restrict__ Hout,
              const __half* __restrict__ Ah, const __half* __restrict__ Bh,
              int M, int N, int K, int mode) {
    extern __shared__ __align__(1024) char smem[];
    const uint32_t sbase = smem_u32(smem);
    const int tid = threadIdx.x;
    const int wid = tid >> 5;
    const int lane = tid & 31;
    const int wm = wid & 3;
    const int wn = wid >> 2;
    const int bm = blockIdx.y * TILE_M;
    const int bn = blockIdx.x * TILE_N;

    const int mi = lane >> 3;
    const int lr = lane & 7;
    const uint32_t a_off = (uint32_t)(wm * 32 + ((mi & 1) << 3) + lr) * 128;
    const uint32_t a_cb = (uint32_t)(mi >> 1);
    const uint32_t b_off = (uint32_t)(wn * 64 + ((mi >> 1) << 3) + lr) * 128;
    const uint32_t b_cb = (uint32_t)(mi & 1);

    float acc[2][8][4];
#pragma unroll
    for (int a = 0; a < 2; a++)
#pragma unroll
        for (int b = 0; b < 8; b++)
#pragma unroll
            for (int c = 0; c < 4; c++) acc[a][b][c] = 0.f;

    const int NC = K / KT;

    load_stage(Ah, Bh, K, bm, bn, 0, sbase, tid);
    load_stage(Ah, Bh, K, bm, bn, KT, sbase + STAGE_BYTES, tid);

    for (int kc = 0; kc < NC; kc++) {
        if (kc + 1 < NC) {
            asm volatile("cp.async.wait_group 1;\n" ::: "memory");
        } else {
            asm volatile("cp.async.wait_group 0;\n" ::: "memory");
        }
        __syncthreads();
        if (kc + 2 < NC) {
            load_stage(Ah, Bh, K, bm, bn, (kc + 2) * KT,
                       sbase + (uint32_t)((kc + 2) % 3) * STAGE_BYTES, tid);
        }
        const uint32_t sb = sbase + (uint32_t)(kc % 3) * STAGE_BYTES;

#pragma unroll
        for (int ki = 0; ki < 4; ki++) {
            uint32_t ah[2][4], bh[4][4];
            const uint32_t ax = ((uint32_t)(ki * 2) + a_cb) ^ (uint32_t)lr;
            const uint32_t bx = ((uint32_t)(ki * 2) + b_cb) ^ (uint32_t)lr;
#pragma unroll
            for (int mt = 0; mt < 2; mt++) {
                uint32_t aaddr = sb + a_off + (uint32_t)(mt * 2048) + (ax << 4);
                ldsm4(ah[mt], aaddr);
            }
#pragma unroll
            for (int nt = 0; nt < 4; nt++) {
                uint32_t baddr = sb + OFF_B + b_off + (uint32_t)(nt * 2048) + (bx << 4);
                ldsm4(bh[nt], baddr);
            }
#pragma unroll
            for (int mt = 0; mt < 2; mt++)
#pragma unroll
                for (int nt = 0; nt < 4; nt++)
#pragma unroll
                    for (int h = 0; h < 2; h++)
                        mma_fp16(acc[mt][nt * 2 + h], ah[mt],
                                 bh[nt][2 * h], bh[nt][2 * h + 1]);
        }
    }

    const int g = lane >> 2;
    const int t = lane & 3;
    if (mode == 1) {
        // stage 128x128 halves in smem, then coalesced 16B stores
        __syncthreads();
        __half* sh = (__half*)smem;
#pragma unroll
        for (int mt = 0; mt < 2; mt++) {
            const int r0 = wm * 32 + mt * 16 + g;
#pragma unroll
            for (int n8 = 0; n8 < 8; n8++) {
                const int colh = wn * 32 + n8 * 4 + t;
                float* c = acc[mt][n8];
                sh[r0 * 128 + colh] =
                    __float2half_rn((c[0] / (1.f + __expf(-c[0]))) * c[1]);
                sh[(r0 + 8) * 128 + colh] =
                    __float2half_rn((c[2] / (1.f + __expf(-c[2]))) * c[3]);
            }
        }
        __syncthreads();
        const int NH = N >> 1;
        const uint4* s4 = (const uint4*)smem;
#pragma unroll
        for (int i = tid; i < 128 * 16; i += GTHREADS) {
            int r = i >> 4;
            int cpos = i & 15;
            *(uint4*)(Hout + (size_t)(bm + r) * NH + (bn >> 1) + cpos * 8) = s4[i];
        }
    } else {
#pragma unroll
        for (int mt = 0; mt < 2; mt++) {
            const int row0 = bm + wm * 32 + mt * 16 + g;
#pragma unroll
            for (int n8 = 0; n8 < 8; n8++) {
                const int col = bn + wn * 64 + n8 * 8 + t * 2;
                float* c = acc[mt][n8];
                if (R) {
                    const float* r0 = R + (size_t)row0 * N + col;
                    const float* r1 = R + (size_t)(row0 + 8) * N + col;
                    *(float2*)(C + (size_t)row0 * N + col) =
                        make_float2(c[0] + r0[0], c[1] + r0[1]);
                    *(float2*)(C + (size_t)(row0 + 8) * N + col) =
                        make_float2(c[2] + r1[0], c[3] + r1[1]);
                } else {
                    *(float2*)(C + (size_t)row0 * N + col)       = make_float2(c[0], c[1]);
                    *(float2*)(C + (size_t)(row0 + 8) * N + col) = make_float2(c[2], c[3]);
                }
            }
        }
    }
}

// ---------------- fp32 -> fp16 stores ----------------------------------------
__device__ __forceinline__ void store_h4(__half* hi, int i4, float4 v) {
    ((__half2*)hi)[2 * i4]     = __halves2half2(__float2half_rn(v.x), __float2half_rn(v.y));
    ((__half2*)hi)[2 * i4 + 1] = __halves2half2(__float2half_rn(v.z), __float2half_rn(v.w));
}

__global__ void cvt_w_k(const float* __restrict__ x, __half* __restrict__ hi, int n4) {
    int i = blockIdx.x * 256 + threadIdx.x;
    if (i >= n4) return;
    store_h4(hi, i, ((const float4*)x)[i]);
}

__global__ void cvt_qkvg_k(const float* __restrict__ qw, const float* __restrict__ kw,
                           const float* __restrict__ vw, const float* __restrict__ gw,
                           __half* __restrict__ hi) {
    int i = blockIdx.x * 256 + threadIdx.x;
    int region = i >> 18;                          // CC*CC/4 = 262144
    int j = i & 0x3FFFF;
    const float* src = (region == 0) ? qw : (region == 1) ? kw : (region == 2) ? vw : gw;
    store_h4(hi + ((size_t)region << 20), j, ((const float4*)src)[j]);
}

#define ROW4 (CC/4)
__global__ void cvt_gu_k(const float* __restrict__ fg, const float* __restrict__ fu,
                         __half* __restrict__ hi) {
    int i = blockIdx.x * 256 + threadIdx.x;
    int row = i / ROW4;
    int pos = i % ROW4;
    store_h4(hi, (2 * row) * ROW4 + pos, ((const float4*)fg)[i]);
    store_h4(hi, (2 * row + 1) * ROW4 + pos, ((const float4*)fu)[i]);
}

// ---------------- rmsnorm (fp16 output fused) ---------------------------------
__global__ void rmsnorm_h_k(const float* __restrict__ x, const float* __restrict__ w,
                            float* __restrict__ y, __half* __restrict__ hi) {
    int row = blockIdx.x;
    const float* xr = x + (size_t)row * CC;
    float* yr = y + (size_t)row * CC;
    float v[4];
    float ss = 0.f;
#pragma unroll
    for (int i = 0; i < 4; i++) {
        v[i] = xr[threadIdx.x + i * 256];
        ss += v[i] * v[i];
    }
#pragma unroll
    for (int off = 16; off; off >>= 1) ss += __shfl_xor_sync(0xffffffffu, ss, off);
    __shared__ float sred[8];
    __shared__ float stot;
    if ((threadIdx.x & 31) == 0) sred[threadIdx.x >> 5] = ss;
    __syncthreads();
    if (threadIdx.x < 8) {
        float t = sred[threadIdx.x];
#pragma unroll
        for (int off = 4; off; off >>= 1) t += __shfl_xor_sync(0xffu, t, off);
        if (threadIdx.x == 0) stot = t;
    }
    __syncthreads();
    float r = rsqrtf(stot / (float)CC + 1e-6f);
#pragma unroll
    for (int i = 0; i < 4; i++)
        yr[threadIdx.x + i * 256] = v[i] * r * w[threadIdx.x + i * 256];
    __syncthreads();
    float4 vv = ((const float4*)yr)[threadIdx.x];
    store_h4(hi + (size_t)row * CC, threadIdx.x, vv);
}

// ---------------- beta (R13 form: measured 48us) ------------------------------
__global__ __launch_bounds__(512)
void beta_k(const float* __restrict__ xn, const float* __restrict__ bw,
            const float* __restrict__ bias, float* __restrict__ beta) {
    __shared__ float xs[CC];
    const int row = blockIdx.x;
    for (int i = threadIdx.x; i < CC; i += 512) xs[i] = xn[(size_t)row * CC + i];
    __syncthreads();
    const int h = threadIdx.x >> 5;
    const int lane = threadIdx.x & 31;
    const float* w = bw + (size_t)h * CC;
    float acc = 0.f;
#pragma unroll 8
    for (int j = lane; j < CC; j += 32) acc += xs[j] * w[j];
#pragma unroll
    for (int off = 16; off; off >>= 1) acc += __shfl_xor_sync(0xffffffffu, acc, off);
    if (lane == 0) {
        float t = acc + bias[h];
        beta[(size_t)row * HH + h] = 1.f / (1.f + __expf(-t));
    }
}

// ---------------- l2norm over q,k (merged QKVG layout, ld=4096) --------------
__global__ void l2norm_qk_k(float* __restrict__ ff) {
    int vec = blockIdx.x * 8 + (threadIdx.x >> 5);
    int lane = threadIdx.x & 31;
    int row = vec >> 5;
    int seg = vec & 31;
    float* p = ff + (size_t)row * 4096 + seg * 64;
    float a = p[lane], b = p[lane + 32];
    float ss = a * a + b * b;
#pragma unroll
    for (int off = 16; off; off >>= 1) ss += __shfl_xor_sync(0xffffffffu, ss, off);
    float inv = 1.f / fmaxf(sqrtf(ss), 1e-12f);
    p[lane] = a * inv;
    p[lane + 32] = b * inv;
}

// sigmoid(gate)*o -> fp16 (gate at ff col 3072, ld 4096)
__global__ void gate_mul_h_k(const float* __restrict__ ff, const float* __restrict__ o,
                             __half* __restrict__ hi) {
    int row = blockIdx.x;
    int t = threadIdx.x;
    float4 gv = ((const float4*)(ff + (size_t)row * 4096 + 3072))[t];
    float4 ov = ((const float4*)(o + (size_t)row * CC))[t];
    float4 r;
    r.x = ov.x / (1.f + __expf(-gv.x));
    r.y = ov.y / (1.f + __expf(-gv.y));
    r.z = ov.z / (1.f + __expf(-gv.z));
    r.w = ov.w / (1.f + __expf(-gv.w));
    store_h4(hi + (size_t)row * CC, t, r);
}

// ---------------- delta-rule scan (q/k/v in merged layout, ld=4096) ----------
__global__ __launch_bounds__(128)
void delta_scan_k(const float* __restrict__ ff, const float* __restrict__ beta,
                  float* __restrict__ o) {
    const int b = blockIdx.x / HH;
    const int h = blockIdx.x % HH;
    const int tid = threadIdx.x;
    const int d = tid >> 1;
    const int s = tid & 1;
    const int cbase = s * 32;
    const int LD = 4096;

    __shared__ float qs[2][64];
    __shared__ float ks[2][64];

    float Mrow[32];
#pragma unroll
    for (int j = 0; j < 32; j++) Mrow[j] = 0.f;

    const float* qb = ff + (size_t)b * TT * LD + h * DD;
    const float* kb = qb + 1024;
    const float* vb = qb + 2048;
    const float* bb = beta + (size_t)b * TT * HH + h;
    float* ob = o + (size_t)b * TT * CC + h * DD;

    float rqk = (tid < 64) ? qb[tid] : kb[tid - 64];
    float rv = vb[d];
    float rb = bb[0];

    int buf = 0;
    for (int t = 0; t < TT; t++) {
        if (tid < 64) qs[buf][tid] = rqk; else ks[buf][tid - 64] = rqk;
        __syncthreads();
        float cv = rv, cb = rb;
        if (t + 1 < TT) {
            const size_t off = (size_t)(t + 1) * LD;
            rqk = (tid < 64) ? qb[off + tid] : kb[off + tid - 64];
            rv = vb[off + d];
            rb = bb[(t + 1) * HH];
        }
        float po0 = 0.f, po1 = 0.f, pm0 = 0.f, pm1 = 0.f;
#pragma unroll
        for (int j = 0; j < 32; j += 2) {
            float q0 = qs[buf][cbase + j], q1 = qs[buf][cbase + j + 1];
            float k0 = ks[buf][cbase + j], k1 = ks[buf][cbase + j + 1];
            po0 += Mrow[j] * q0;
            po1 += Mrow[j + 1] * q1;
            pm0 += Mrow[j] * k0;
            pm1 += Mrow[j + 1] * k1;
        }
        float po = po0 + po1, pm = pm0 + pm1;
        po += __shfl_xor_sync(0xffffffffu, po, 1);
        pm += __shfl_xor_sync(0xffffffffu, pm, 1);
        float dvb = cb * (cv - pm);
#pragma unroll
        for (int j = 0; j < 32; j++) Mrow[j] += dvb * ks[buf][cbase + j];
        if (s == 0) ob[(size_t)t * CC + d] = po;
        buf ^= 1;
    }
}

// ---------------- launch ------------------------------------------------------
extern "C" void kernel_launch(void* const* d_in, const int* in_sizes, int n_in,
                              void* d_out, int out_size) {
    const float* x       = (const float*)d_in[0];
    const float* norm1_w = (const float*)d_in[3];
    const float* norm2_w = (const float*)d_in[4];
    const float* q_w     = (const float*)d_in[5];
    const float* k_w     = (const float*)d_in[6];
    const float* v_w     = (const float*)d_in[7];
    const float* beta_w  = (const float*)d_in[8];
    const float* beta_b  = (const float*)d_in[9];
    const float* gate_w  = (const float*)d_in[10];
    const float* o_w     = (const float*)d_in[11];
    const float* fg_w    = (const float*)d_in[12];
    const float* fu_w    = (const float*)d_in[13];
    const float* fd_w    = (const float*)d_in[14];
    float* out = (float*)d_out;

    float *xn, *o, *x1, *beta, *ff;
    __half *ah, *swi, *w_qkvg, *w_o, *w_gu, *w_d;
    cudaGetSymbolAddress((void**)&xn,     g_xn);
    cudaGetSymbolAddress((void**)&o,      g_o);
    cudaGetSymbolAddress((void**)&x1,     g_x1);
    cudaGetSymbolAddress((void**)&beta,   g_beta);
    cudaGetSymbolAddress((void**)&ff,     g_ff);
    cudaGetSymbolAddress((void**)&ah,     g_a_hi);
    cudaGetSymbolAddress((void**)&swi,    g_swi);
    cudaGetSymbolAddress((void**)&w_qkvg, g_w_qkvg);
    cudaGetSymbolAddress((void**)&w_o,    g_w_o);
    cudaGetSymbolAddress((void**)&w_gu,   g_w_gu);
    cudaGetSymbolAddress((void**)&w_d,    g_w_d);

    cudaFuncSetAttribute(gemm_mma, cudaFuncAttributeMaxDynamicSharedMemorySize,
                         GSMEM_TOTAL);

    // streams/events: created once on first (uncaptured) call, reused in capture
    static cudaStream_t s1 = nullptr, s2 = nullptr;
    static cudaEvent_t ev_root = nullptr, ev_qkvg = nullptr, ev_o = nullptr,
                       ev_gu = nullptr, ev_d = nullptr, ev_xn = nullptr,
                       ev_beta = nullptr;
    if (!s1) {
        cudaStreamCreateWithFlags(&s1, cudaStreamNonBlocking);
        cudaStreamCreateWithFlags(&s2, cudaStreamNonBlocking);
        cudaEventCreateWithFlags(&ev_root, cudaEventDisableTiming);
        cudaEventCreateWithFlags(&ev_qkvg, cudaEventDisableTiming);
        cudaEventCreateWithFlags(&ev_o,    cudaEventDisableTiming);
        cudaEventCreateWithFlags(&ev_gu,   cudaEventDisableTiming);
        cudaEventCreateWithFlags(&ev_d,    cudaEventDisableTiming);
        cudaEventCreateWithFlags(&ev_xn,   cudaEventDisableTiming);
        cudaEventCreateWithFlags(&ev_beta, cudaEventDisableTiming);
    }

    auto gemm = [&](float* Cm, const float* R, __half* H, const __half* A,
                    const __half* W, int N, int K, int mode) {
        gemm_mma<<<dim3(N / TILE_N, MROWS / TILE_M), GTHREADS, GSMEM_TOTAL>>>(
            Cm, R, H, A, W, MROWS, N, K, mode);
    };

    // ---- fork side stream for all weight converts (input-only) ----
    cudaEventRecord(ev_root, 0);
    cudaStreamWaitEvent(s1, ev_root, 0);
    cudaStreamWaitEvent(s2, ev_root, 0);
    cvt_qkvg_k<<<4 * (CC * CC / 4) / 256, 256, 0, s1>>>(q_w, k_w, v_w, gate_w, w_qkvg);
    cudaEventRecord(ev_qkvg, s1);
    cvt_w_k<<<(CC * CC / 4) / 256, 256, 0, s1>>>(o_w, w_o, CC * CC / 4);
    cudaEventRecord(ev_o, s1);
    cvt_gu_k<<<(FF * CC / 4) / 256, 256, 0, s1>>>(fg_w, fu_w, w_gu);
    cudaEventRecord(ev_gu, s1);
    cvt_w_k<<<(FF * CC / 4) / 256, 256, 0, s1>>>(fd_w, w_d, FF * CC / 4);
    cudaEventRecord(ev_d, s1);

    // ---- attention branch (main stream) ----
    rmsnorm_h_k<<<MROWS, 256>>>(x, norm1_w, xn, ah);
    cudaEventRecord(ev_xn, 0);
    // beta on s2, overlapped with QKVG gemm
    cudaStreamWaitEvent(s2, ev_xn, 0);
    beta_k<<<MROWS, 512, 0, s2>>>(xn, beta_w, beta_b, beta);
    cudaEventRecord(ev_beta, s2);

    cudaStreamWaitEvent(0, ev_qkvg, 0);
    gemm(ff, nullptr, nullptr, ah, w_qkvg, 4 * CC, CC, 0);   // QKVG, ld=4096
    l2norm_qk_k<<<(MROWS * 32) / 8, 256>>>(ff);
    cudaStreamWaitEvent(0, ev_beta, 0);
    delta_scan_k<<<BB * HH, 128>>>(ff, beta, o);
    gate_mul_h_k<<<MROWS, 256>>>(ff, o, ah);
    cudaStreamWaitEvent(0, ev_o, 0);
    gemm(x1, x, nullptr, ah, w_o, CC, CC, 0);                // x1 = x + attn_out

    // ---- FFN branch ----
    rmsnorm_h_k<<<MROWS, 256>>>(x1, norm2_w, xn, ah);
    cudaStreamWaitEvent(0, ev_gu, 0);
    gemm(nullptr, nullptr, swi, ah, w_gu, 2 * FF, CC, 1);    // fused SwiGLU -> swi
    cudaStreamWaitEvent(0, ev_d, 0);
    gemm(out, x1, nullptr, swi, w_d, CC, FF, 0);             // out = x1 + ffn_out
}